// round 2
// baseline (speedup 1.0000x reference)
#include <cuda_runtime.h>
#include <math.h>

#define SEQ 4096
#define DIM 1024
#define NH 8
#define HD 128
#define WIN 512
#define SCALING 0.0625f
#define SOFTCAP 50.0f
#define EPSV 1e-6f
#define NEGV -1e30f

// scratch (allocation-free rule: device globals)
__device__ float g_q[SEQ * DIM];
__device__ float g_k[SEQ * DIM];
__device__ float g_v[SEQ * DIM];
__device__ float g_attn[SEQ * DIM];

// ---------------------------------------------------------------------------
// SGEMM NT: C[M,N] = A[M,K] @ B[N,K]^T, all row-major, fp32.
// BM=128, BN=64, BK=16, 256 threads, 8x4 per-thread tile.
// ---------------------------------------------------------------------------
__global__ __launch_bounds__(256) void sgemm_nt(
    const float* __restrict__ A, const float* __restrict__ B,
    float* __restrict__ C, int M, int N, int K)
{
    const int BM = 128, BN = 64, BK = 16;
    __shared__ float As[BK][BM];
    __shared__ float Bs[BK][BN];

    int tid = threadIdx.x;
    int tx = tid & 15;        // 0..15 -> N
    int ty = tid >> 4;        // 0..15 -> M
    int m0 = blockIdx.y * BM;
    int n0 = blockIdx.x * BN;

    float acc[8][4];
#pragma unroll
    for (int i = 0; i < 8; ++i)
#pragma unroll
        for (int j = 0; j < 4; ++j) acc[i][j] = 0.0f;

    for (int k0 = 0; k0 < K; k0 += BK) {
        // A tile: 128x16 = 512 float4, 2 per thread
#pragma unroll
        for (int i = 0; i < 2; ++i) {
            int f = tid + i * 256;
            int row = f >> 2;
            int k4 = (f & 3) * 4;
            float4 va = *(const float4*)&A[(size_t)(m0 + row) * K + k0 + k4];
            As[k4 + 0][row] = va.x;
            As[k4 + 1][row] = va.y;
            As[k4 + 2][row] = va.z;
            As[k4 + 3][row] = va.w;
        }
        // B tile: 64x16 = 256 float4, 1 per thread
        {
            int row = tid >> 2;
            int k4 = (tid & 3) * 4;
            float4 vb = *(const float4*)&B[(size_t)(n0 + row) * K + k0 + k4];
            Bs[k4 + 0][row] = vb.x;
            Bs[k4 + 1][row] = vb.y;
            Bs[k4 + 2][row] = vb.z;
            Bs[k4 + 3][row] = vb.w;
        }
        __syncthreads();
#pragma unroll
        for (int kk = 0; kk < BK; ++kk) {
            float4 a0 = *(const float4*)&As[kk][ty * 8];
            float4 a1 = *(const float4*)&As[kk][ty * 8 + 4];
            float4 b0 = *(const float4*)&Bs[kk][tx * 4];
            float ar[8] = {a0.x, a0.y, a0.z, a0.w, a1.x, a1.y, a1.z, a1.w};
            float br[4] = {b0.x, b0.y, b0.z, b0.w};
#pragma unroll
            for (int i = 0; i < 8; ++i)
#pragma unroll
                for (int j = 0; j < 4; ++j)
                    acc[i][j] += ar[i] * br[j];
        }
        __syncthreads();
    }
#pragma unroll
    for (int i = 0; i < 8; ++i) {
        float4 o = make_float4(acc[i][0], acc[i][1], acc[i][2], acc[i][3]);
        *(float4*)&C[(size_t)(m0 + ty * 8 + i) * N + n0 + tx * 4] = o;
    }
}

// ---------------------------------------------------------------------------
// Fused RMSNorm + RoPE on q/k, in place. grid (S, H, 2), block 128.
// ---------------------------------------------------------------------------
__global__ void rmsnorm_rope(
    float* __restrict__ q, float* __restrict__ k,
    const float* __restrict__ qw, const float* __restrict__ kw,
    const float* __restrict__ cosd, const float* __restrict__ sind)
{
    int s = blockIdx.x;
    int h = blockIdx.y;
    int which = blockIdx.z;
    int d = threadIdx.x;

    float* buf = which ? k : q;
    const float* w = which ? kw : qw;
    float* x = buf + (size_t)s * DIM + h * HD;

    float xd = x[d];
    int p = d ^ 64;
    float xp = x[p];

    float v = xd * xd;
#pragma unroll
    for (int off = 16; off; off >>= 1)
        v += __shfl_xor_sync(0xffffffffu, v, off);
    __shared__ float red[4];
    if ((d & 31) == 0) red[d >> 5] = v;
    __syncthreads();
    float var = (red[0] + red[1] + red[2] + red[3]) * (1.0f / HD);
    float rs = rsqrtf(var + EPSV);

    float xnd = xd * rs * (1.0f + w[d]);
    float xnp = xp * rs * (1.0f + w[p]);
    float c = cosd[(size_t)s * HD + d];
    float si = sind[(size_t)s * HD + d];
    float rot = (d < 64) ? -xnp : xnp;
    float outv = xnd * c + rot * si;
    __syncthreads();   // all cross-thread reads done before in-place write
    x[d] = outv;
}

// ---------------------------------------------------------------------------
// Windowed attention. CTA = (64 queries, 1 head). Score slab 64x576 in smem.
// ---------------------------------------------------------------------------
#define QBLK 64
#define KT 64
#define NTILE 9
#define SLABW 580    // multiple of 4: float4 ops on slab rows must stay 16B-aligned
#define QKS 68       // stride (floats) for Qs/Ks [d][row], 16B-aligned rows
#define VSTR 132     // stride (floats) for Vs [key][d]

#define SMEM_FLOATS (QBLK * SLABW + HD * QKS + HD * QKS)
#define SMEM_BYTES  (SMEM_FLOATS * 4)

__global__ __launch_bounds__(256) void attn_kernel(
    const float* __restrict__ qb, const float* __restrict__ kb,
    const float* __restrict__ vb,
    float* __restrict__ probs, float* __restrict__ attn)
{
    extern __shared__ float sm[];
    float* slab = sm;                       // 64 x 580
    float* Qs = sm + QBLK * SLABW;          // 128 x 68 ([d][row])
    float* Ks = Qs + HD * QKS;              // 128 x 68 ([d][key]) / Vs 64x132
    __shared__ float rowscale[QBLK];

    int qb0 = blockIdx.x * QBLK;
    int h = blockIdx.y;
    int tid = threadIdx.x;
    int kbase = qb0 - WIN;
    int t_start = (qb0 >= WIN) ? 0 : (WIN - qb0) / KT;
    int c0 = t_start * KT;

    // load Q transposed: Qs[d][m]
#pragma unroll
    for (int i = 0; i < 8; ++i) {
        int f = tid + i * 256;
        int row = f >> 5;              // 0..63
        int d4 = (f & 31) * 4;         // 0..124
        float4 v = *(const float4*)&qb[(size_t)(qb0 + row) * DIM + h * HD + d4];
        Qs[(d4 + 0) * QKS + row] = v.x;
        Qs[(d4 + 1) * QKS + row] = v.y;
        Qs[(d4 + 2) * QKS + row] = v.z;
        Qs[(d4 + 3) * QKS + row] = v.w;
    }

    int tx = tid & 15;
    int ty = tid >> 4;

    // ---- scores ----
    for (int t = t_start; t < NTILE; ++t) {
        __syncthreads();
        // K tile transposed: Ks[d][key]
#pragma unroll
        for (int i = 0; i < 8; ++i) {
            int f = tid + i * 256;
            int row = f >> 5;
            int d4 = (f & 31) * 4;
            int j = kbase + t * KT + row;
            int jc = j < 0 ? 0 : j;
            float4 v = *(const float4*)&kb[(size_t)jc * DIM + h * HD + d4];
            Ks[(d4 + 0) * QKS + row] = v.x;
            Ks[(d4 + 1) * QKS + row] = v.y;
            Ks[(d4 + 2) * QKS + row] = v.z;
            Ks[(d4 + 3) * QKS + row] = v.w;
        }
        __syncthreads();

        float acc[4][4];
#pragma unroll
        for (int i = 0; i < 4; ++i)
#pragma unroll
            for (int j = 0; j < 4; ++j) acc[i][j] = 0.0f;

#pragma unroll 8
        for (int kk = 0; kk < HD; ++kk) {
            float4 a = *(const float4*)&Qs[kk * QKS + ty * 4];
            float4 b = *(const float4*)&Ks[kk * QKS + tx * 4];
            float ar[4] = {a.x, a.y, a.z, a.w};
            float br[4] = {b.x, b.y, b.z, b.w};
#pragma unroll
            for (int i = 0; i < 4; ++i)
#pragma unroll
                for (int j = 0; j < 4; ++j)
                    acc[i][j] += ar[i] * br[j];
        }

#pragma unroll
        for (int i = 0; i < 4; ++i) {
            int qi = qb0 + ty * 4 + i;
#pragma unroll
            for (int j = 0; j < 4; ++j) {
                int kj = kbase + t * KT + tx * 4 + j;
                float s = acc[i][j] * SCALING;
                s = SOFTCAP * tanhf(s * (1.0f / SOFTCAP));
                bool ok = (kj >= 0) && (kj <= qi) && (qi - kj < WIN);
                slab[(ty * 4 + i) * SLABW + t * KT + tx * 4 + j] = ok ? s : NEGV;
            }
        }
    }
    __syncthreads();

    // ---- softmax (exact; per-warp rows) ----
    int warp = tid >> 5, lane = tid & 31;
    for (int r = warp * 8; r < warp * 8 + 8; ++r) {
        float m = NEGV;
        for (int c = c0 + lane; c < NTILE * KT; c += 32)
            m = fmaxf(m, slab[r * SLABW + c]);
#pragma unroll
        for (int off = 16; off; off >>= 1)
            m = fmaxf(m, __shfl_xor_sync(0xffffffffu, m, off));
        float ssum = 0.0f;
        for (int c = c0 + lane; c < NTILE * KT; c += 32) {
            float e = expf(slab[r * SLABW + c] - m);
            slab[r * SLABW + c] = e;
            ssum += e;
        }
#pragma unroll
        for (int off = 16; off; off >>= 1)
            ssum += __shfl_xor_sync(0xffffffffu, ssum, off);
        if (lane == 0) rowscale[r] = 1.0f / ssum;
    }
    __syncthreads();

    // ---- write probs band (rest is pre-zeroed by memset) ----
    for (int f = tid; f < QBLK * (NTILE * KT / 4); f += 256) {
        int row = f / (NTILE * KT / 4);
        int col = (f % (NTILE * KT / 4)) * 4;
        if (col < c0) continue;
        int j = kbase + col;
        float sc = rowscale[row];
        float4 e = *(const float4*)&slab[row * SLABW + col];
        float4 o = make_float4(e.x * sc, e.y * sc, e.z * sc, e.w * sc);
        *(float4*)&probs[(size_t)h * SEQ * SEQ + (size_t)(qb0 + row) * SEQ + j] = o;
    }

    // ---- PV ----
    float o[4][8];
#pragma unroll
    for (int i = 0; i < 4; ++i)
#pragma unroll
        for (int c = 0; c < 8; ++c) o[i][c] = 0.0f;

    for (int t = t_start; t < NTILE; ++t) {
        __syncthreads();
        // V tile: Vs[key][d] (reuse Ks buffer, stride VSTR)
#pragma unroll
        for (int i = 0; i < 8; ++i) {
            int f = tid + i * 256;
            int row = f >> 5;
            int d4 = (f & 31) * 4;
            int j = kbase + t * KT + row;
            int jc = j < 0 ? 0 : j;
            float4 v = *(const float4*)&vb[(size_t)jc * DIM + h * HD + d4];
            *(float4*)&Ks[row * VSTR + d4] = v;
        }
        __syncthreads();

#pragma unroll 4
        for (int kk = 0; kk < KT; ++kk) {
            float e0 = slab[(ty * 4 + 0) * SLABW + t * KT + kk];
            float e1 = slab[(ty * 4 + 1) * SLABW + t * KT + kk];
            float e2 = slab[(ty * 4 + 2) * SLABW + t * KT + kk];
            float e3 = slab[(ty * 4 + 3) * SLABW + t * KT + kk];
            float4 v0 = *(const float4*)&Ks[kk * VSTR + tx * 8];
            float4 v1 = *(const float4*)&Ks[kk * VSTR + tx * 8 + 4];
            float vr[8] = {v0.x, v0.y, v0.z, v0.w, v1.x, v1.y, v1.z, v1.w};
            float er[4] = {e0, e1, e2, e3};
#pragma unroll
            for (int i = 0; i < 4; ++i)
#pragma unroll
                for (int c = 0; c < 8; ++c)
                    o[i][c] += er[i] * vr[c];
        }
    }

    // ---- write O (scaled) to attn scratch [s][h*128+d] ----
#pragma unroll
    for (int i = 0; i < 4; ++i) {
        int r = ty * 4 + i;
        float sc = rowscale[r];
        float4 w0 = make_float4(o[i][0] * sc, o[i][1] * sc, o[i][2] * sc, o[i][3] * sc);
        float4 w1 = make_float4(o[i][4] * sc, o[i][5] * sc, o[i][6] * sc, o[i][7] * sc);
        float* dst = &attn[(size_t)(qb0 + r) * DIM + h * HD + tx * 8];
        *(float4*)&dst[0] = w0;
        *(float4*)&dst[4] = w1;
    }
}

// ---------------------------------------------------------------------------
extern "C" void kernel_launch(void* const* d_in, const int* in_sizes, int n_in,
                              void* d_out, int out_size)
{
    (void)in_sizes; (void)n_in; (void)out_size;
    const float* hidden = (const float*)d_in[0];
    const float* cosd   = (const float*)d_in[1];
    const float* sind   = (const float*)d_in[2];
    const float* Wq     = (const float*)d_in[3];
    const float* Wk     = (const float*)d_in[4];
    const float* Wv     = (const float*)d_in[5];
    const float* Wo     = (const float*)d_in[6];
    const float* qw     = (const float*)d_in[7];
    const float* kw     = (const float*)d_in[8];

    float* out = (float*)d_out;
    float* probs = out + (size_t)SEQ * DIM;

    float *qp, *kp, *vp, *ap;
    cudaGetSymbolAddress((void**)&qp, g_q);
    cudaGetSymbolAddress((void**)&kp, g_k);
    cudaGetSymbolAddress((void**)&vp, g_v);
    cudaGetSymbolAddress((void**)&ap, g_attn);

    // zero the probs region (band gets overwritten by attn_kernel)
    cudaMemsetAsync(probs, 0, (size_t)NH * SEQ * SEQ * sizeof(float), 0);

    dim3 gproj(DIM / 64, SEQ / 128);
    sgemm_nt<<<gproj, 256>>>(hidden, Wq, qp, SEQ, DIM, DIM);
    sgemm_nt<<<gproj, 256>>>(hidden, Wk, kp, SEQ, DIM, DIM);
    sgemm_nt<<<gproj, 256>>>(hidden, Wv, vp, SEQ, DIM, DIM);

    rmsnorm_rope<<<dim3(SEQ, NH, 2), HD>>>(qp, kp, qw, kw, cosd, sind);

    cudaFuncSetAttribute(attn_kernel,
                         cudaFuncAttributeMaxDynamicSharedMemorySize, SMEM_BYTES);
    attn_kernel<<<dim3(SEQ / QBLK, NH), 256, SMEM_BYTES>>>(qp, kp, vp, probs, ap);

    sgemm_nt<<<gproj, 256>>>(ap, Wo, out, SEQ, DIM, DIM);
}

// round 4
// speedup vs baseline: 1.6639x; 1.6639x over previous
#include <cuda_runtime.h>
#include <cuda_bf16.h>
#include <cstdint>
#include <cstddef>
#include <math.h>

#define SEQ 4096
#define DIM 1024
#define NH 8
#define HD 128
#define WIN 512
#define SCALING 0.0625f
#define SOFTCAP 50.0f
#define EPSV 1e-6f
#define NEGV -1e30f

// scratch (allocation-free rule: device globals)
__device__ float g_q[SEQ * DIM];
__device__ float g_k[SEQ * DIM];
__device__ float g_v[SEQ * DIM];
__device__ float g_attn[SEQ * DIM];
__device__ __align__(16) __nv_bfloat16 g_ah[SEQ * DIM];
__device__ __align__(16) __nv_bfloat16 g_al[SEQ * DIM];
__device__ __align__(16) __nv_bfloat16 g_wh[DIM * DIM];
__device__ __align__(16) __nv_bfloat16 g_wl[DIM * DIM];

// ---------------------------------------------------------------------------
// fp32 -> (bf16 hi, bf16 lo) split
// ---------------------------------------------------------------------------
__global__ void split_kernel(const float* __restrict__ x,
                             __nv_bfloat16* __restrict__ hi,
                             __nv_bfloat16* __restrict__ lo, int n)
{
    int i = (blockIdx.x * blockDim.x + threadIdx.x) * 4;
    if (i >= n) return;
    float4 v = *(const float4*)&x[i];
    __nv_bfloat16 h0 = __float2bfloat16_rn(v.x);
    __nv_bfloat16 h1 = __float2bfloat16_rn(v.y);
    __nv_bfloat16 h2 = __float2bfloat16_rn(v.z);
    __nv_bfloat16 h3 = __float2bfloat16_rn(v.w);
    hi[i + 0] = h0; hi[i + 1] = h1; hi[i + 2] = h2; hi[i + 3] = h3;
    lo[i + 0] = __float2bfloat16_rn(v.x - __bfloat162float(h0));
    lo[i + 1] = __float2bfloat16_rn(v.y - __bfloat162float(h1));
    lo[i + 2] = __float2bfloat16_rn(v.z - __bfloat162float(h2));
    lo[i + 3] = __float2bfloat16_rn(v.w - __bfloat162float(h3));
}

// ---------------------------------------------------------------------------
// split-bf16 tensor-core GEMM: C[M,N] = A[M,K] @ B[N,K]^T (fp32 result)
// hi*hi + hi*lo + lo*hi accumulation -> ~fp32 precision.
// BM=BN=128, BK=32, 256 threads, warps 2(m) x 4(n), warp tile 64x32.
// ---------------------------------------------------------------------------
#define GBM 128
#define GBN 128
#define GBK 32
#define ASTR 40   // smem row stride in bf16 (80B): conflict-free ldmatrix

__device__ __forceinline__ void ldsm4(uint32_t& r0, uint32_t& r1,
                                      uint32_t& r2, uint32_t& r3, uint32_t addr)
{
    asm volatile("ldmatrix.sync.aligned.m8n8.x4.shared.b16 {%0,%1,%2,%3}, [%4];"
                 : "=r"(r0), "=r"(r1), "=r"(r2), "=r"(r3) : "r"(addr));
}

__device__ __forceinline__ void mma_bf16(float& c0, float& c1, float& c2, float& c3,
                                         uint32_t a0, uint32_t a1, uint32_t a2, uint32_t a3,
                                         uint32_t b0, uint32_t b1)
{
    asm volatile(
        "mma.sync.aligned.m16n8k16.row.col.f32.bf16.bf16.f32 "
        "{%0,%1,%2,%3},{%4,%5,%6,%7},{%8,%9},{%0,%1,%2,%3};"
        : "+f"(c0), "+f"(c1), "+f"(c2), "+f"(c3)
        : "r"(a0), "r"(a1), "r"(a2), "r"(a3), "r"(b0), "r"(b1));
}

__global__ __launch_bounds__(256) void gemm_split(
    const __nv_bfloat16* __restrict__ Ah, const __nv_bfloat16* __restrict__ Al,
    const __nv_bfloat16* __restrict__ Bh, const __nv_bfloat16* __restrict__ Bl,
    float* __restrict__ C, int M, int N, int K)
{
    __shared__ __nv_bfloat16 sAh[GBM * ASTR];
    __shared__ __nv_bfloat16 sAl[GBM * ASTR];
    __shared__ __nv_bfloat16 sBh[GBN * ASTR];
    __shared__ __nv_bfloat16 sBl[GBN * ASTR];

    int tid = threadIdx.x;
    int lane = tid & 31;
    int w = tid >> 5;
    int wm = w & 1;          // 0..1 -> m 64-block
    int wn = w >> 1;         // 0..3 -> n 32-block
    int m0 = blockIdx.y * GBM;
    int n0 = blockIdx.x * GBN;

    float c[4][4][4] = {};

    int g = lane >> 3, r8 = lane & 7;
    int a_row_off = (g & 1) * 8;
    int a_k_off = (g >> 1) * 8;
    int b_n_off = (g >> 1) * 8;
    int b_k_off = (g & 1) * 8;

    for (int k0 = 0; k0 < K; k0 += GBK) {
        // global -> smem (each thread: 2 uint4 per operand array)
#pragma unroll
        for (int p = 0; p < 2; ++p) {
            int idx = tid + p * 256;
            int row = idx >> 2;
            int cc = (idx & 3) * 8;
            *(uint4*)&sAh[row * ASTR + cc] =
                *(const uint4*)&Ah[(size_t)(m0 + row) * K + k0 + cc];
            *(uint4*)&sAl[row * ASTR + cc] =
                *(const uint4*)&Al[(size_t)(m0 + row) * K + k0 + cc];
            *(uint4*)&sBh[row * ASTR + cc] =
                *(const uint4*)&Bh[(size_t)(n0 + row) * K + k0 + cc];
            *(uint4*)&sBl[row * ASTR + cc] =
                *(const uint4*)&Bl[(size_t)(n0 + row) * K + k0 + cc];
        }
        __syncthreads();

#pragma unroll
        for (int ks = 0; ks < GBK; ks += 16) {
            uint32_t ah[4][4], al[4][4], bh[4][2], bl[4][2];
#pragma unroll
            for (int mt = 0; mt < 4; ++mt) {
                int roff = (wm * 64 + mt * 16 + a_row_off + r8) * ASTR + ks + a_k_off;
                uint32_t sa = (uint32_t)__cvta_generic_to_shared(&sAh[roff]);
                ldsm4(ah[mt][0], ah[mt][1], ah[mt][2], ah[mt][3], sa);
                uint32_t sl = (uint32_t)__cvta_generic_to_shared(&sAl[roff]);
                ldsm4(al[mt][0], al[mt][1], al[mt][2], al[mt][3], sl);
            }
#pragma unroll
            for (int ntp = 0; ntp < 2; ++ntp) {
                int roff = (wn * 32 + ntp * 16 + b_n_off + r8) * ASTR + ks + b_k_off;
                uint32_t sb = (uint32_t)__cvta_generic_to_shared(&sBh[roff]);
                ldsm4(bh[ntp * 2][0], bh[ntp * 2][1], bh[ntp * 2 + 1][0], bh[ntp * 2 + 1][1], sb);
                uint32_t sc = (uint32_t)__cvta_generic_to_shared(&sBl[roff]);
                ldsm4(bl[ntp * 2][0], bl[ntp * 2][1], bl[ntp * 2 + 1][0], bl[ntp * 2 + 1][1], sc);
            }
#pragma unroll
            for (int mt = 0; mt < 4; ++mt)
#pragma unroll
                for (int nt = 0; nt < 4; ++nt) {
                    float* cc = c[mt][nt];
                    mma_bf16(cc[0], cc[1], cc[2], cc[3],
                             ah[mt][0], ah[mt][1], ah[mt][2], ah[mt][3],
                             bh[nt][0], bh[nt][1]);
                    mma_bf16(cc[0], cc[1], cc[2], cc[3],
                             ah[mt][0], ah[mt][1], ah[mt][2], ah[mt][3],
                             bl[nt][0], bl[nt][1]);
                    mma_bf16(cc[0], cc[1], cc[2], cc[3],
                             al[mt][0], al[mt][1], al[mt][2], al[mt][3],
                             bh[nt][0], bh[nt][1]);
                }
        }
        __syncthreads();
    }

    // epilogue: direct fp32 stores (c0,c1 contiguous pairs)
#pragma unroll
    for (int mt = 0; mt < 4; ++mt) {
#pragma unroll
        for (int nt = 0; nt < 4; ++nt) {
            int row = m0 + wm * 64 + mt * 16 + (lane >> 2);
            int col = n0 + wn * 32 + nt * 8 + 2 * (lane & 3);
            float* cc = c[mt][nt];
            *(float2*)&C[(size_t)row * N + col] = make_float2(cc[0], cc[1]);
            *(float2*)&C[(size_t)(row + 8) * N + col] = make_float2(cc[2], cc[3]);
        }
    }
}

// ---------------------------------------------------------------------------
// Fused RMSNorm + RoPE on q/k, in place. grid (S, H, 2), block 128.
// ---------------------------------------------------------------------------
__global__ void rmsnorm_rope(
    float* __restrict__ q, float* __restrict__ k,
    const float* __restrict__ qw, const float* __restrict__ kw,
    const float* __restrict__ cosd, const float* __restrict__ sind)
{
    int s = blockIdx.x;
    int h = blockIdx.y;
    int which = blockIdx.z;
    int d = threadIdx.x;

    float* buf = which ? k : q;
    const float* w = which ? kw : qw;
    float* x = buf + (size_t)s * DIM + h * HD;

    float xd = x[d];
    int p = d ^ 64;
    float xp = x[p];

    float v = xd * xd;
#pragma unroll
    for (int off = 16; off; off >>= 1)
        v += __shfl_xor_sync(0xffffffffu, v, off);
    __shared__ float red[4];
    if ((d & 31) == 0) red[d >> 5] = v;
    __syncthreads();
    float var = (red[0] + red[1] + red[2] + red[3]) * (1.0f / HD);
    float rs = rsqrtf(var + EPSV);

    float xnd = xd * rs * (1.0f + w[d]);
    float xnp = xp * rs * (1.0f + w[p]);
    float c = cosd[(size_t)s * HD + d];
    float si = sind[(size_t)s * HD + d];
    float rot = (d < 64) ? -xnp : xnp;
    float outv = xnd * c + rot * si;
    __syncthreads();   // all cross-thread reads done before in-place write
    x[d] = outv;
}

// ---------------------------------------------------------------------------
// Windowed attention. CTA = (64 queries, 1 head). Score slab 64x576 in smem.
// ---------------------------------------------------------------------------
#define QBLK 64
#define KT 64
#define NTILE 9
#define SLABW 580    // multiple of 4: float4 slab ops stay 16B-aligned
#define QKS 68
#define VSTR 132

#define SMEM_FLOATS (QBLK * SLABW + HD * QKS + HD * QKS)
#define SMEM_BYTES  (SMEM_FLOATS * 4)

__global__ __launch_bounds__(256) void attn_kernel(
    const float* __restrict__ qb, const float* __restrict__ kb,
    const float* __restrict__ vb,
    float* __restrict__ probs, float* __restrict__ attn)
{
    extern __shared__ float sm[];
    float* slab = sm;
    float* Qs = sm + QBLK * SLABW;
    float* Ks = Qs + HD * QKS;
    __shared__ float rowscale[QBLK];

    int qb0 = blockIdx.x * QBLK;
    int h = blockIdx.y;
    int tid = threadIdx.x;
    int kbase = qb0 - WIN;
    int t_start = (qb0 >= WIN) ? 0 : (WIN - qb0) / KT;
    int c0 = t_start * KT;

#pragma unroll
    for (int i = 0; i < 8; ++i) {
        int f = tid + i * 256;
        int row = f >> 5;
        int d4 = (f & 31) * 4;
        float4 v = *(const float4*)&qb[(size_t)(qb0 + row) * DIM + h * HD + d4];
        Qs[(d4 + 0) * QKS + row] = v.x;
        Qs[(d4 + 1) * QKS + row] = v.y;
        Qs[(d4 + 2) * QKS + row] = v.z;
        Qs[(d4 + 3) * QKS + row] = v.w;
    }

    int tx = tid & 15;
    int ty = tid >> 4;

    for (int t = t_start; t < NTILE; ++t) {
        __syncthreads();
#pragma unroll
        for (int i = 0; i < 8; ++i) {
            int f = tid + i * 256;
            int row = f >> 5;
            int d4 = (f & 31) * 4;
            int j = kbase + t * KT + row;
            int jc = j < 0 ? 0 : j;
            float4 v = *(const float4*)&kb[(size_t)jc * DIM + h * HD + d4];
            Ks[(d4 + 0) * QKS + row] = v.x;
            Ks[(d4 + 1) * QKS + row] = v.y;
            Ks[(d4 + 2) * QKS + row] = v.z;
            Ks[(d4 + 3) * QKS + row] = v.w;
        }
        __syncthreads();

        float acc[4][4];
#pragma unroll
        for (int i = 0; i < 4; ++i)
#pragma unroll
            for (int j = 0; j < 4; ++j) acc[i][j] = 0.0f;

#pragma unroll 8
        for (int kk = 0; kk < HD; ++kk) {
            float4 a = *(const float4*)&Qs[kk * QKS + ty * 4];
            float4 b = *(const float4*)&Ks[kk * QKS + tx * 4];
            float ar[4] = {a.x, a.y, a.z, a.w};
            float br[4] = {b.x, b.y, b.z, b.w};
#pragma unroll
            for (int i = 0; i < 4; ++i)
#pragma unroll
                for (int j = 0; j < 4; ++j)
                    acc[i][j] += ar[i] * br[j];
        }

#pragma unroll
        for (int i = 0; i < 4; ++i) {
            int qi = qb0 + ty * 4 + i;
#pragma unroll
            for (int j = 0; j < 4; ++j) {
                int kj = kbase + t * KT + tx * 4 + j;
                float s = acc[i][j] * SCALING;
                s = SOFTCAP * tanhf(s * (1.0f / SOFTCAP));
                bool ok = (kj >= 0) && (kj <= qi) && (qi - kj < WIN);
                slab[(ty * 4 + i) * SLABW + t * KT + tx * 4 + j] = ok ? s : NEGV;
            }
        }
    }
    __syncthreads();

    int warp = tid >> 5, lane = tid & 31;
    for (int r = warp * 8; r < warp * 8 + 8; ++r) {
        float m = NEGV;
        for (int c = c0 + lane; c < NTILE * KT; c += 32)
            m = fmaxf(m, slab[r * SLABW + c]);
#pragma unroll
        for (int off = 16; off; off >>= 1)
            m = fmaxf(m, __shfl_xor_sync(0xffffffffu, m, off));
        float ssum = 0.0f;
        for (int c = c0 + lane; c < NTILE * KT; c += 32) {
            float e = expf(slab[r * SLABW + c] - m);
            slab[r * SLABW + c] = e;
            ssum += e;
        }
#pragma unroll
        for (int off = 16; off; off >>= 1)
            ssum += __shfl_xor_sync(0xffffffffu, ssum, off);
        if (lane == 0) rowscale[r] = 1.0f / ssum;
    }
    __syncthreads();

    for (int f = tid; f < QBLK * (NTILE * KT / 4); f += 256) {
        int row = f / (NTILE * KT / 4);
        int col = (f % (NTILE * KT / 4)) * 4;
        if (col < c0) continue;
        int j = kbase + col;
        float sc = rowscale[row];
        float4 e = *(const float4*)&slab[row * SLABW + col];
        float4 o = make_float4(e.x * sc, e.y * sc, e.z * sc, e.w * sc);
        *(float4*)&probs[(size_t)h * SEQ * SEQ + (size_t)(qb0 + row) * SEQ + j] = o;
    }

    float o[4][8];
#pragma unroll
    for (int i = 0; i < 4; ++i)
#pragma unroll
        for (int c = 0; c < 8; ++c) o[i][c] = 0.0f;

    for (int t = t_start; t < NTILE; ++t) {
        __syncthreads();
#pragma unroll
        for (int i = 0; i < 8; ++i) {
            int f = tid + i * 256;
            int row = f >> 5;
            int d4 = (f & 31) * 4;
            int j = kbase + t * KT + row;
            int jc = j < 0 ? 0 : j;
            float4 v = *(const float4*)&vb[(size_t)jc * DIM + h * HD + d4];
            *(float4*)&Ks[row * VSTR + d4] = v;
        }
        __syncthreads();

#pragma unroll 4
        for (int kk = 0; kk < KT; ++kk) {
            float e0 = slab[(ty * 4 + 0) * SLABW + t * KT + kk];
            float e1 = slab[(ty * 4 + 1) * SLABW + t * KT + kk];
            float e2 = slab[(ty * 4 + 2) * SLABW + t * KT + kk];
            float e3 = slab[(ty * 4 + 3) * SLABW + t * KT + kk];
            float4 v0 = *(const float4*)&Ks[kk * VSTR + tx * 8];
            float4 v1 = *(const float4*)&Ks[kk * VSTR + tx * 8 + 4];
            float vr[8] = {v0.x, v0.y, v0.z, v0.w, v1.x, v1.y, v1.z, v1.w};
            float er[4] = {e0, e1, e2, e3};
#pragma unroll
            for (int i = 0; i < 4; ++i)
#pragma unroll
                for (int c = 0; c < 8; ++c)
                    o[i][c] += er[i] * vr[c];
        }
    }

#pragma unroll
    for (int i = 0; i < 4; ++i) {
        int r = ty * 4 + i;
        float sc = rowscale[r];
        float4 w0 = make_float4(o[i][0] * sc, o[i][1] * sc, o[i][2] * sc, o[i][3] * sc);
        float4 w1 = make_float4(o[i][4] * sc, o[i][5] * sc, o[i][6] * sc, o[i][7] * sc);
        float* dst = &attn[(size_t)(qb0 + r) * DIM + h * HD + tx * 8];
        *(float4*)&dst[0] = w0;
        *(float4*)&dst[4] = w1;
    }
}

// ---------------------------------------------------------------------------
extern "C" void kernel_launch(void* const* d_in, const int* in_sizes, int n_in,
                              void* d_out, int out_size)
{
    (void)in_sizes; (void)n_in; (void)out_size;
    const float* hidden = (const float*)d_in[0];
    const float* cosd   = (const float*)d_in[1];
    const float* sind   = (const float*)d_in[2];
    const float* Wq     = (const float*)d_in[3];
    const float* Wk     = (const float*)d_in[4];
    const float* Wv     = (const float*)d_in[5];
    const float* Wo     = (const float*)d_in[6];
    const float* qw     = (const float*)d_in[7];
    const float* kw     = (const float*)d_in[8];

    float* out = (float*)d_out;
    float* probs = out + (size_t)SEQ * DIM;

    float *qp, *kp, *vp, *ap;
    cudaGetSymbolAddress((void**)&qp, g_q);
    cudaGetSymbolAddress((void**)&kp, g_k);
    cudaGetSymbolAddress((void**)&vp, g_v);
    cudaGetSymbolAddress((void**)&ap, g_attn);
    __nv_bfloat16 *ah, *al, *wh, *wl;
    cudaGetSymbolAddress((void**)&ah, g_ah);
    cudaGetSymbolAddress((void**)&al, g_al);
    cudaGetSymbolAddress((void**)&wh, g_wh);
    cudaGetSymbolAddress((void**)&wl, g_wl);

    cudaMemsetAsync(probs, 0, (size_t)NH * SEQ * SEQ * sizeof(float), 0);

    const int NELEM_A = SEQ * DIM, NELEM_W = DIM * DIM;
    dim3 ggemm(DIM / GBN, SEQ / GBM);

    split_kernel<<<NELEM_A / 4 / 256, 256>>>(hidden, ah, al, NELEM_A);

    split_kernel<<<NELEM_W / 4 / 256, 256>>>(Wq, wh, wl, NELEM_W);
    gemm_split<<<ggemm, 256>>>(ah, al, wh, wl, qp, SEQ, DIM, DIM);
    split_kernel<<<NELEM_W / 4 / 256, 256>>>(Wk, wh, wl, NELEM_W);
    gemm_split<<<ggemm, 256>>>(ah, al, wh, wl, kp, SEQ, DIM, DIM);
    split_kernel<<<NELEM_W / 4 / 256, 256>>>(Wv, wh, wl, NELEM_W);
    gemm_split<<<ggemm, 256>>>(ah, al, wh, wl, vp, SEQ, DIM, DIM);

    rmsnorm_rope<<<dim3(SEQ, NH, 2), HD>>>(qp, kp, qw, kw, cosd, sind);

    cudaFuncSetAttribute(attn_kernel,
                         cudaFuncAttributeMaxDynamicSharedMemorySize, SMEM_BYTES);
    attn_kernel<<<dim3(SEQ / QBLK, NH), 256, SMEM_BYTES>>>(qp, kp, vp, probs, ap);

    split_kernel<<<NELEM_A / 4 / 256, 256>>>(ap, ah, al, NELEM_A);
    split_kernel<<<NELEM_W / 4 / 256, 256>>>(Wo, wh, wl, NELEM_W);
    gemm_split<<<ggemm, 256>>>(ah, al, wh, wl, out, SEQ, DIM, DIM);
}

// round 5
// speedup vs baseline: 2.3118x; 1.3894x over previous
#include <cuda_runtime.h>
#include <cuda_bf16.h>
#include <cstdint>
#include <cstddef>
#include <math.h>

#define SEQ 4096
#define DIM 1024
#define NH 8
#define HD 128
#define WIN 512
#define SCALING 0.0625f
#define SOFTCAP 50.0f
#define EPSV 1e-6f
#define NEGV -1e30f

// scratch (allocation-free rule: device globals)
__device__ float g_q[SEQ * DIM];
__device__ float g_k[SEQ * DIM];
__device__ float g_v[SEQ * DIM];
__device__ float g_attn[SEQ * DIM];
__device__ __align__(16) __nv_bfloat16 g_ah[SEQ * DIM];
__device__ __align__(16) __nv_bfloat16 g_al[SEQ * DIM];
__device__ __align__(16) __nv_bfloat16 g_wh[DIM * DIM];
__device__ __align__(16) __nv_bfloat16 g_wl[DIM * DIM];
__device__ __align__(16) __nv_bfloat16 g_qh[SEQ * DIM];
__device__ __align__(16) __nv_bfloat16 g_ql[SEQ * DIM];
__device__ __align__(16) __nv_bfloat16 g_kh[SEQ * DIM];
__device__ __align__(16) __nv_bfloat16 g_kl[SEQ * DIM];
__device__ __align__(16) __nv_bfloat16 g_vth[DIM * SEQ];
__device__ __align__(16) __nv_bfloat16 g_vtl[DIM * SEQ];

// ---------------------------------------------------------------------------
// fp32 -> (bf16 hi, bf16 lo) split
// ---------------------------------------------------------------------------
__global__ void split_kernel(const float* __restrict__ x,
                             __nv_bfloat16* __restrict__ hi,
                             __nv_bfloat16* __restrict__ lo, int n)
{
    int i = (blockIdx.x * blockDim.x + threadIdx.x) * 4;
    if (i >= n) return;
    float4 v = *(const float4*)&x[i];
    __nv_bfloat16 h0 = __float2bfloat16_rn(v.x);
    __nv_bfloat16 h1 = __float2bfloat16_rn(v.y);
    __nv_bfloat16 h2 = __float2bfloat16_rn(v.z);
    __nv_bfloat16 h3 = __float2bfloat16_rn(v.w);
    hi[i + 0] = h0; hi[i + 1] = h1; hi[i + 2] = h2; hi[i + 3] = h3;
    lo[i + 0] = __float2bfloat16_rn(v.x - __bfloat162float(h0));
    lo[i + 1] = __float2bfloat16_rn(v.y - __bfloat162float(h1));
    lo[i + 2] = __float2bfloat16_rn(v.z - __bfloat162float(h2));
    lo[i + 3] = __float2bfloat16_rn(v.w - __bfloat162float(h3));
}

// ---------------------------------------------------------------------------
// MMA primitives (validated in round 4)
// ---------------------------------------------------------------------------
__device__ __forceinline__ void ldsm4(uint32_t& r0, uint32_t& r1,
                                      uint32_t& r2, uint32_t& r3, uint32_t addr)
{
    asm volatile("ldmatrix.sync.aligned.m8n8.x4.shared.b16 {%0,%1,%2,%3}, [%4];"
                 : "=r"(r0), "=r"(r1), "=r"(r2), "=r"(r3) : "r"(addr));
}

__device__ __forceinline__ void mma_bf16(float& c0, float& c1, float& c2, float& c3,
                                         uint32_t a0, uint32_t a1, uint32_t a2, uint32_t a3,
                                         uint32_t b0, uint32_t b1)
{
    asm volatile(
        "mma.sync.aligned.m16n8k16.row.col.f32.bf16.bf16.f32 "
        "{%0,%1,%2,%3},{%4,%5,%6,%7},{%8,%9},{%0,%1,%2,%3};"
        : "+f"(c0), "+f"(c1), "+f"(c2), "+f"(c3)
        : "r"(a0), "r"(a1), "r"(a2), "r"(a3), "r"(b0), "r"(b1));
}

// ---------------------------------------------------------------------------
// split-bf16 tensor-core GEMM: C[M,N] = A[M,K] @ B[N,K]^T (fp32 result)
// ---------------------------------------------------------------------------
#define GBM 128
#define GBN 128
#define GBK 32
#define ASTR 40

__global__ __launch_bounds__(256) void gemm_split(
    const __nv_bfloat16* __restrict__ Ah, const __nv_bfloat16* __restrict__ Al,
    const __nv_bfloat16* __restrict__ Bh, const __nv_bfloat16* __restrict__ Bl,
    float* __restrict__ C, int M, int N, int K)
{
    __shared__ __nv_bfloat16 sAh[GBM * ASTR];
    __shared__ __nv_bfloat16 sAl[GBM * ASTR];
    __shared__ __nv_bfloat16 sBh[GBN * ASTR];
    __shared__ __nv_bfloat16 sBl[GBN * ASTR];

    int tid = threadIdx.x;
    int lane = tid & 31;
    int w = tid >> 5;
    int wm = w & 1;
    int wn = w >> 1;
    int m0 = blockIdx.y * GBM;
    int n0 = blockIdx.x * GBN;

    float c[4][4][4] = {};

    int g = lane >> 3, r8 = lane & 7;
    int a_row_off = (g & 1) * 8;
    int a_k_off = (g >> 1) * 8;
    int b_n_off = (g >> 1) * 8;
    int b_k_off = (g & 1) * 8;

    for (int k0 = 0; k0 < K; k0 += GBK) {
#pragma unroll
        for (int p = 0; p < 2; ++p) {
            int idx = tid + p * 256;
            int row = idx >> 2;
            int cc = (idx & 3) * 8;
            *(uint4*)&sAh[row * ASTR + cc] =
                *(const uint4*)&Ah[(size_t)(m0 + row) * K + k0 + cc];
            *(uint4*)&sAl[row * ASTR + cc] =
                *(const uint4*)&Al[(size_t)(m0 + row) * K + k0 + cc];
            *(uint4*)&sBh[row * ASTR + cc] =
                *(const uint4*)&Bh[(size_t)(n0 + row) * K + k0 + cc];
            *(uint4*)&sBl[row * ASTR + cc] =
                *(const uint4*)&Bl[(size_t)(n0 + row) * K + k0 + cc];
        }
        __syncthreads();

#pragma unroll
        for (int ks = 0; ks < GBK; ks += 16) {
            uint32_t ah[4][4], al[4][4], bh[4][2], bl[4][2];
#pragma unroll
            for (int mt = 0; mt < 4; ++mt) {
                int roff = (wm * 64 + mt * 16 + a_row_off + r8) * ASTR + ks + a_k_off;
                uint32_t sa = (uint32_t)__cvta_generic_to_shared(&sAh[roff]);
                ldsm4(ah[mt][0], ah[mt][1], ah[mt][2], ah[mt][3], sa);
                uint32_t sl = (uint32_t)__cvta_generic_to_shared(&sAl[roff]);
                ldsm4(al[mt][0], al[mt][1], al[mt][2], al[mt][3], sl);
            }
#pragma unroll
            for (int ntp = 0; ntp < 2; ++ntp) {
                int roff = (wn * 32 + ntp * 16 + b_n_off + r8) * ASTR + ks + b_k_off;
                uint32_t sb = (uint32_t)__cvta_generic_to_shared(&sBh[roff]);
                ldsm4(bh[ntp * 2][0], bh[ntp * 2][1], bh[ntp * 2 + 1][0], bh[ntp * 2 + 1][1], sb);
                uint32_t sc = (uint32_t)__cvta_generic_to_shared(&sBl[roff]);
                ldsm4(bl[ntp * 2][0], bl[ntp * 2][1], bl[ntp * 2 + 1][0], bl[ntp * 2 + 1][1], sc);
            }
#pragma unroll
            for (int mt = 0; mt < 4; ++mt)
#pragma unroll
                for (int nt = 0; nt < 4; ++nt) {
                    float* cc = c[mt][nt];
                    mma_bf16(cc[0], cc[1], cc[2], cc[3],
                             ah[mt][0], ah[mt][1], ah[mt][2], ah[mt][3],
                             bh[nt][0], bh[nt][1]);
                    mma_bf16(cc[0], cc[1], cc[2], cc[3],
                             ah[mt][0], ah[mt][1], ah[mt][2], ah[mt][3],
                             bl[nt][0], bl[nt][1]);
                    mma_bf16(cc[0], cc[1], cc[2], cc[3],
                             al[mt][0], al[mt][1], al[mt][2], al[mt][3],
                             bh[nt][0], bh[nt][1]);
                }
        }
        __syncthreads();
    }

#pragma unroll
    for (int mt = 0; mt < 4; ++mt) {
#pragma unroll
        for (int nt = 0; nt < 4; ++nt) {
            int row = m0 + wm * 64 + mt * 16 + (lane >> 2);
            int col = n0 + wn * 32 + nt * 8 + 2 * (lane & 3);
            float* cc = c[mt][nt];
            *(float2*)&C[(size_t)row * N + col] = make_float2(cc[0], cc[1]);
            *(float2*)&C[(size_t)(row + 8) * N + col] = make_float2(cc[2], cc[3]);
        }
    }
}

// ---------------------------------------------------------------------------
// Fused RMSNorm + RoPE; emits split bf16 (hi,lo). grid (S, H, 2), block 128.
// ---------------------------------------------------------------------------
__global__ void rmsnorm_rope_split(
    const float* __restrict__ q, const float* __restrict__ k,
    const float* __restrict__ qw, const float* __restrict__ kw,
    const float* __restrict__ cosd, const float* __restrict__ sind,
    __nv_bfloat16* __restrict__ qh, __nv_bfloat16* __restrict__ ql,
    __nv_bfloat16* __restrict__ kh, __nv_bfloat16* __restrict__ kl)
{
    int s = blockIdx.x;
    int h = blockIdx.y;
    int which = blockIdx.z;
    int d = threadIdx.x;

    const float* buf = which ? k : q;
    const float* w = which ? kw : qw;
    __nv_bfloat16* oh = which ? kh : qh;
    __nv_bfloat16* ol = which ? kl : ql;
    const float* x = buf + (size_t)s * DIM + h * HD;

    float xd = x[d];
    int p = d ^ 64;
    float xp = x[p];

    float v = xd * xd;
#pragma unroll
    for (int off = 16; off; off >>= 1)
        v += __shfl_xor_sync(0xffffffffu, v, off);
    __shared__ float red[4];
    if ((d & 31) == 0) red[d >> 5] = v;
    __syncthreads();
    float var = (red[0] + red[1] + red[2] + red[3]) * (1.0f / HD);
    float rs = rsqrtf(var + EPSV);

    float xnd = xd * rs * (1.0f + w[d]);
    float xnp = xp * rs * (1.0f + w[p]);
    float c = cosd[(size_t)s * HD + d];
    float si = sind[(size_t)s * HD + d];
    float rot = (d < 64) ? -xnp : xnp;
    float outv = xnd * c + rot * si;

    size_t idx = (size_t)s * DIM + h * HD + d;
    __nv_bfloat16 hh = __float2bfloat16_rn(outv);
    oh[idx] = hh;
    ol[idx] = __float2bfloat16_rn(outv - __bfloat162float(hh));
}

// ---------------------------------------------------------------------------
// V transpose + split: g_v [s][dglobal] fp32 -> vth/vtl [dglobal][s] bf16
// ---------------------------------------------------------------------------
__global__ void vt_split(const float* __restrict__ v,
                         __nv_bfloat16* __restrict__ vth,
                         __nv_bfloat16* __restrict__ vtl)
{
    __shared__ float tile[32][33];
    int d0 = blockIdx.x * 32;
    int s0 = blockIdx.y * 32;
    int tx = threadIdx.x, ty = threadIdx.y;
#pragma unroll
    for (int i = 0; i < 4; ++i) {
        int s = s0 + ty + i * 8;
        tile[ty + i * 8][tx] = v[(size_t)s * DIM + d0 + tx];
    }
    __syncthreads();
#pragma unroll
    for (int i = 0; i < 4; ++i) {
        int d = d0 + ty + i * 8;
        int s = s0 + tx;
        float val = tile[tx][ty + i * 8];
        __nv_bfloat16 hh = __float2bfloat16_rn(val);
        vth[(size_t)d * SEQ + s] = hh;
        vtl[(size_t)d * SEQ + s] = __float2bfloat16_rn(val - __bfloat162float(hh));
    }
}

// ---------------------------------------------------------------------------
// Windowed attention, tensor-core version.
// CTA = 64 queries x 1 head, 256 threads (8 warps).
// ---------------------------------------------------------------------------
#define QBLK 64
#define KT 64
#define NTILE 9
#define SLABW 580
#define QKSTR 136   // Q/K smem tile stride (bf16): 272B, 16 mod 128 -> LDSM clean
#define PSTR 72     // P / V^T smem tile stride (bf16): 144B, 16 mod 128

#define ATT_A_OFF (QBLK * SLABW * 4)                 // 148480
#define ATT_B_OFF (ATT_A_OFF + 2 * QBLK * QKSTR * 2) // +34816 = 183296
#define ATT_SMEM  (ATT_B_OFF + 2 * HD * PSTR * 2)    // +36864 = 220160

__global__ __launch_bounds__(256) void attn_kernel(
    const __nv_bfloat16* __restrict__ gqh, const __nv_bfloat16* __restrict__ gql,
    const __nv_bfloat16* __restrict__ gkh, const __nv_bfloat16* __restrict__ gkl,
    const __nv_bfloat16* __restrict__ gvth, const __nv_bfloat16* __restrict__ gvtl,
    float* __restrict__ probs, float* __restrict__ attn)
{
    extern __shared__ char smc[];
    float* slab = (float*)smc;                              // 64 x 580 fp32
    __nv_bfloat16* Qh = (__nv_bfloat16*)(smc + ATT_A_OFF);  // 64 x 136
    __nv_bfloat16* Ql = Qh + QBLK * QKSTR;
    __nv_bfloat16* Ph = (__nv_bfloat16*)(smc + ATT_A_OFF);  // alias (after scores)
    __nv_bfloat16* Pl = Ph + QBLK * PSTR;
    __nv_bfloat16* Kh = (__nv_bfloat16*)(smc + ATT_B_OFF);  // 64 x 136
    __nv_bfloat16* Kl = Kh + QBLK * QKSTR;
    __nv_bfloat16* Vh = (__nv_bfloat16*)(smc + ATT_B_OFF);  // alias: 128 x 72
    __nv_bfloat16* Vl = Vh + HD * PSTR;
    __shared__ float rowscale[QBLK];

    int qb0 = blockIdx.x * QBLK;
    int h = blockIdx.y;
    int tid = threadIdx.x;
    int lane = tid & 31;
    int w = tid >> 5;
    int wm = w & 3;          // m 16-block (4)
    int wn = w >> 2;         // n-half (2)
    int kbase = qb0 - WIN;
    int t_start = (qb0 >= WIN) ? 0 : (WIN - qb0) / KT;
    int c0 = t_start * KT;

    int g = lane >> 3, r8 = lane & 7;
    int a_row_off = (g & 1) * 8;
    int a_k_off = (g >> 1) * 8;
    int b_n_off = (g >> 1) * 8;
    int b_k_off = (g & 1) * 8;
    int qg = lane >> 2, t4 = lane & 3;   // output fragment coords

    // ---- load Q tiles (hi/lo) ----
#pragma unroll
    for (int i = 0; i < 4; ++i) {
        int idx = tid + i * 256;
        int row = idx >> 4;
        int c8 = (idx & 15) * 8;
        size_t goff = (size_t)(qb0 + row) * DIM + h * HD + c8;
        *(uint4*)&Qh[row * QKSTR + c8] = *(const uint4*)&gqh[goff];
        *(uint4*)&Ql[row * QKSTR + c8] = *(const uint4*)&gql[goff];
    }

    // ================= scores =================
    for (int t = t_start; t < NTILE; ++t) {
        __syncthreads();
#pragma unroll
        for (int i = 0; i < 4; ++i) {
            int idx = tid + i * 256;
            int row = idx >> 4;
            int c8 = (idx & 15) * 8;
            size_t goff = (size_t)(kbase + t * KT + row) * DIM + h * HD + c8;
            *(uint4*)&Kh[row * QKSTR + c8] = *(const uint4*)&gkh[goff];
            *(uint4*)&Kl[row * QKSTR + c8] = *(const uint4*)&gkl[goff];
        }
        __syncthreads();

        float acc[4][4] = {};
#pragma unroll
        for (int ks = 0; ks < 8; ++ks) {
            uint32_t qhf[4], qlf[4], bhf[4][2], blf[4][2];
            int aoff = (wm * 16 + a_row_off + r8) * QKSTR + ks * 16 + a_k_off;
            ldsm4(qhf[0], qhf[1], qhf[2], qhf[3],
                  (uint32_t)__cvta_generic_to_shared(&Qh[aoff]));
            ldsm4(qlf[0], qlf[1], qlf[2], qlf[3],
                  (uint32_t)__cvta_generic_to_shared(&Ql[aoff]));
#pragma unroll
            for (int ntp = 0; ntp < 2; ++ntp) {
                int boff = (wn * 32 + ntp * 16 + b_n_off + r8) * QKSTR + ks * 16 + b_k_off;
                ldsm4(bhf[ntp * 2][0], bhf[ntp * 2][1],
                      bhf[ntp * 2 + 1][0], bhf[ntp * 2 + 1][1],
                      (uint32_t)__cvta_generic_to_shared(&Kh[boff]));
                ldsm4(blf[ntp * 2][0], blf[ntp * 2][1],
                      blf[ntp * 2 + 1][0], blf[ntp * 2 + 1][1],
                      (uint32_t)__cvta_generic_to_shared(&Kl[boff]));
            }
#pragma unroll
            for (int nt = 0; nt < 4; ++nt) {
                float* cc = acc[nt];
                mma_bf16(cc[0], cc[1], cc[2], cc[3],
                         qhf[0], qhf[1], qhf[2], qhf[3], bhf[nt][0], bhf[nt][1]);
                mma_bf16(cc[0], cc[1], cc[2], cc[3],
                         qhf[0], qhf[1], qhf[2], qhf[3], blf[nt][0], blf[nt][1]);
                mma_bf16(cc[0], cc[1], cc[2], cc[3],
                         qlf[0], qlf[1], qlf[2], qlf[3], bhf[nt][0], bhf[nt][1]);
            }
        }

        // epilogue: softcap + mask -> slab
#pragma unroll
        for (int nt = 0; nt < 4; ++nt) {
#pragma unroll
            for (int e = 0; e < 4; ++e) {
                int r = wm * 16 + qg + (e >> 1) * 8;
                int cw = wn * 32 + nt * 8 + 2 * t4 + (e & 1);
                int qi = qb0 + r;
                int kj = kbase + t * KT + cw;
                float x = acc[nt][e] * (SCALING / SOFTCAP);
                float ex = __expf(2.0f * x);
                float sv = SOFTCAP * __fdividef(ex - 1.0f, ex + 1.0f);
                bool ok = (kj <= qi) && (qi - kj < WIN);
                slab[r * SLABW + t * KT + cw] = ok ? sv : NEGV;
            }
        }
    }
    __syncthreads();

    // ================= softmax (exact) =================
    for (int r = w * 8; r < w * 8 + 8; ++r) {
        float m = NEGV;
        for (int c = c0 + lane; c < NTILE * KT; c += 32)
            m = fmaxf(m, slab[r * SLABW + c]);
#pragma unroll
        for (int off = 16; off; off >>= 1)
            m = fmaxf(m, __shfl_xor_sync(0xffffffffu, m, off));
        float ssum = 0.0f;
        for (int c = c0 + lane; c < NTILE * KT; c += 32) {
            float e = __expf(slab[r * SLABW + c] - m);
            slab[r * SLABW + c] = e;
            ssum += e;
        }
#pragma unroll
        for (int off = 16; off; off >>= 1)
            ssum += __shfl_xor_sync(0xffffffffu, ssum, off);
        if (lane == 0) rowscale[r] = 1.0f / ssum;
    }
    __syncthreads();

    // ================= probs band write =================
    for (int f = tid; f < QBLK * (NTILE * KT / 4); f += 256) {
        int row = f / (NTILE * KT / 4);
        int col = (f % (NTILE * KT / 4)) * 4;
        if (col < c0) continue;
        int j = kbase + col;
        float sc = rowscale[row];
        float4 e = *(const float4*)&slab[row * SLABW + col];
        float4 o = make_float4(e.x * sc, e.y * sc, e.z * sc, e.w * sc);
        *(float4*)&probs[(size_t)h * SEQ * SEQ + (size_t)(qb0 + row) * SEQ + j] = o;
    }

    // ================= P @ V (tensor) =================
    float oacc[8][4] = {};
    for (int t = t_start; t < NTILE; ++t) {
        __syncthreads();   // prior-iter ldsm done before Ph/Vh overwrite
        // convert P tile (exp values) -> split bf16
#pragma unroll
        for (int i = 0; i < 4; ++i) {
            int idx = tid + i * 256;
            int row = idx >> 4;
            int c4 = (idx & 15) * 4;
            float4 p = *(const float4*)&slab[row * SLABW + t * KT + c4];
            __nv_bfloat16 h0 = __float2bfloat16_rn(p.x);
            __nv_bfloat16 h1 = __float2bfloat16_rn(p.y);
            __nv_bfloat16 h2 = __float2bfloat16_rn(p.z);
            __nv_bfloat16 h3 = __float2bfloat16_rn(p.w);
            Ph[row * PSTR + c4 + 0] = h0;
            Ph[row * PSTR + c4 + 1] = h1;
            Ph[row * PSTR + c4 + 2] = h2;
            Ph[row * PSTR + c4 + 3] = h3;
            Pl[row * PSTR + c4 + 0] = __float2bfloat16_rn(p.x - __bfloat162float(h0));
            Pl[row * PSTR + c4 + 1] = __float2bfloat16_rn(p.y - __bfloat162float(h1));
            Pl[row * PSTR + c4 + 2] = __float2bfloat16_rn(p.z - __bfloat162float(h2));
            Pl[row * PSTR + c4 + 3] = __float2bfloat16_rn(p.w - __bfloat162float(h3));
        }
        // load V^T tile: [128 d][64 keys]
        int kstart = kbase + t * KT;
#pragma unroll
        for (int i = 0; i < 4; ++i) {
            int idx = tid + i * 256;
            int row = idx >> 3;
            int c8 = (idx & 7) * 8;
            size_t goff = (size_t)(h * HD + row) * SEQ + kstart + c8;
            *(uint4*)&Vh[row * PSTR + c8] = *(const uint4*)&gvth[goff];
            *(uint4*)&Vl[row * PSTR + c8] = *(const uint4*)&gvtl[goff];
        }
        __syncthreads();

#pragma unroll
        for (int ks = 0; ks < 4; ++ks) {
            uint32_t phf[4], plf[4], vhf[8][2], vlf[8][2];
            int aoff = (wm * 16 + a_row_off + r8) * PSTR + ks * 16 + a_k_off;
            ldsm4(phf[0], phf[1], phf[2], phf[3],
                  (uint32_t)__cvta_generic_to_shared(&Ph[aoff]));
            ldsm4(plf[0], plf[1], plf[2], plf[3],
                  (uint32_t)__cvta_generic_to_shared(&Pl[aoff]));
#pragma unroll
            for (int ntp = 0; ntp < 4; ++ntp) {
                int boff = (wn * 64 + ntp * 16 + b_n_off + r8) * PSTR + ks * 16 + b_k_off;
                ldsm4(vhf[ntp * 2][0], vhf[ntp * 2][1],
                      vhf[ntp * 2 + 1][0], vhf[ntp * 2 + 1][1],
                      (uint32_t)__cvta_generic_to_shared(&Vh[boff]));
                ldsm4(vlf[ntp * 2][0], vlf[ntp * 2][1],
                      vlf[ntp * 2 + 1][0], vlf[ntp * 2 + 1][1],
                      (uint32_t)__cvta_generic_to_shared(&Vl[boff]));
            }
#pragma unroll
            for (int nt = 0; nt < 8; ++nt) {
                float* cc = oacc[nt];
                mma_bf16(cc[0], cc[1], cc[2], cc[3],
                         phf[0], phf[1], phf[2], phf[3], vhf[nt][0], vhf[nt][1]);
                mma_bf16(cc[0], cc[1], cc[2], cc[3],
                         phf[0], phf[1], phf[2], phf[3], vlf[nt][0], vlf[nt][1]);
                mma_bf16(cc[0], cc[1], cc[2], cc[3],
                         plf[0], plf[1], plf[2], plf[3], vhf[nt][0], vhf[nt][1]);
            }
        }
    }

    // ---- write O (scaled by 1/rowsum) ----
    {
        int r0 = wm * 16 + qg;
        int r1 = r0 + 8;
        float sc0 = rowscale[r0];
        float sc1 = rowscale[r1];
#pragma unroll
        for (int nt = 0; nt < 8; ++nt) {
            int col = wn * 64 + nt * 8 + 2 * t4;
            float* cc = oacc[nt];
            *(float2*)&attn[(size_t)(qb0 + r0) * DIM + h * HD + col] =
                make_float2(cc[0] * sc0, cc[1] * sc0);
            *(float2*)&attn[(size_t)(qb0 + r1) * DIM + h * HD + col] =
                make_float2(cc[2] * sc1, cc[3] * sc1);
        }
    }
}

// ---------------------------------------------------------------------------
extern "C" void kernel_launch(void* const* d_in, const int* in_sizes, int n_in,
                              void* d_out, int out_size)
{
    (void)in_sizes; (void)n_in; (void)out_size;
    const float* hidden = (const float*)d_in[0];
    const float* cosd   = (const float*)d_in[1];
    const float* sind   = (const float*)d_in[2];
    const float* Wq     = (const float*)d_in[3];
    const float* Wk     = (const float*)d_in[4];
    const float* Wv     = (const float*)d_in[5];
    const float* Wo     = (const float*)d_in[6];
    const float* qw     = (const float*)d_in[7];
    const float* kw     = (const float*)d_in[8];

    float* out = (float*)d_out;
    float* probs = out + (size_t)SEQ * DIM;

    float *qp, *kp, *vp, *ap;
    cudaGetSymbolAddress((void**)&qp, g_q);
    cudaGetSymbolAddress((void**)&kp, g_k);
    cudaGetSymbolAddress((void**)&vp, g_v);
    cudaGetSymbolAddress((void**)&ap, g_attn);
    __nv_bfloat16 *ah, *al, *wh, *wl, *qh, *ql, *kh, *kl, *vth, *vtl;
    cudaGetSymbolAddress((void**)&ah, g_ah);
    cudaGetSymbolAddress((void**)&al, g_al);
    cudaGetSymbolAddress((void**)&wh, g_wh);
    cudaGetSymbolAddress((void**)&wl, g_wl);
    cudaGetSymbolAddress((void**)&qh, g_qh);
    cudaGetSymbolAddress((void**)&ql, g_ql);
    cudaGetSymbolAddress((void**)&kh, g_kh);
    cudaGetSymbolAddress((void**)&kl, g_kl);
    cudaGetSymbolAddress((void**)&vth, g_vth);
    cudaGetSymbolAddress((void**)&vtl, g_vtl);

    cudaMemsetAsync(probs, 0, (size_t)NH * SEQ * SEQ * sizeof(float), 0);

    const int NELEM_A = SEQ * DIM, NELEM_W = DIM * DIM;
    dim3 ggemm(DIM / GBN, SEQ / GBM);

    split_kernel<<<NELEM_A / 4 / 256, 256>>>(hidden, ah, al, NELEM_A);

    split_kernel<<<NELEM_W / 4 / 256, 256>>>(Wq, wh, wl, NELEM_W);
    gemm_split<<<ggemm, 256>>>(ah, al, wh, wl, qp, SEQ, DIM, DIM);
    split_kernel<<<NELEM_W / 4 / 256, 256>>>(Wk, wh, wl, NELEM_W);
    gemm_split<<<ggemm, 256>>>(ah, al, wh, wl, kp, SEQ, DIM, DIM);
    split_kernel<<<NELEM_W / 4 / 256, 256>>>(Wv, wh, wl, NELEM_W);
    gemm_split<<<ggemm, 256>>>(ah, al, wh, wl, vp, SEQ, DIM, DIM);

    rmsnorm_rope_split<<<dim3(SEQ, NH, 2), HD>>>(qp, kp, qw, kw, cosd, sind,
                                                 qh, ql, kh, kl);
    vt_split<<<dim3(DIM / 32, SEQ / 32), dim3(32, 8)>>>(vp, vth, vtl);

    cudaFuncSetAttribute(attn_kernel,
                         cudaFuncAttributeMaxDynamicSharedMemorySize, ATT_SMEM);
    attn_kernel<<<dim3(SEQ / QBLK, NH), 256, ATT_SMEM>>>(qh, ql, kh, kl, vth, vtl,
                                                         probs, ap);

    split_kernel<<<NELEM_A / 4 / 256, 256>>>(ap, ah, al, NELEM_A);
    split_kernel<<<NELEM_W / 4 / 256, 256>>>(Wo, wh, wl, NELEM_W);
    gemm_split<<<ggemm, 256>>>(ah, al, wh, wl, out, SEQ, DIM, DIM);
}

// round 6
// speedup vs baseline: 2.3648x; 1.0229x over previous
#include <cuda_runtime.h>
#include <cuda_bf16.h>
#include <cstdint>
#include <cstddef>
#include <math.h>

#define SEQ 4096
#define DIM 1024
#define NH 8
#define HD 128
#define WIN 512
#define SCALING 0.0625f
#define SOFTCAP 50.0f
#define EPSV 1e-6f
#define NEGV -1e30f

// scratch (allocation-free rule: device globals)
__device__ float g_q[SEQ * DIM];
__device__ float g_k[SEQ * DIM];
__device__ float g_v[SEQ * DIM];
__device__ float g_attn[SEQ * DIM];
__device__ __align__(16) __nv_bfloat16 g_ah[SEQ * DIM];
__device__ __align__(16) __nv_bfloat16 g_al[SEQ * DIM];
__device__ __align__(16) __nv_bfloat16 g_wh[DIM * DIM];
__device__ __align__(16) __nv_bfloat16 g_wl[DIM * DIM];
__device__ __align__(16) __nv_bfloat16 g_qh[SEQ * DIM];
__device__ __align__(16) __nv_bfloat16 g_ql[SEQ * DIM];
__device__ __align__(16) __nv_bfloat16 g_kh[SEQ * DIM];
__device__ __align__(16) __nv_bfloat16 g_kl[SEQ * DIM];
__device__ __align__(16) __nv_bfloat16 g_vth[DIM * SEQ];
__device__ __align__(16) __nv_bfloat16 g_vtl[DIM * SEQ];

// ---------------------------------------------------------------------------
// fp32 -> (bf16 hi, bf16 lo) split
// ---------------------------------------------------------------------------
__global__ void split_kernel(const float* __restrict__ x,
                             __nv_bfloat16* __restrict__ hi,
                             __nv_bfloat16* __restrict__ lo, int n)
{
    int i = (blockIdx.x * blockDim.x + threadIdx.x) * 4;
    if (i >= n) return;
    float4 v = *(const float4*)&x[i];
    __nv_bfloat16 h0 = __float2bfloat16_rn(v.x);
    __nv_bfloat16 h1 = __float2bfloat16_rn(v.y);
    __nv_bfloat16 h2 = __float2bfloat16_rn(v.z);
    __nv_bfloat16 h3 = __float2bfloat16_rn(v.w);
    hi[i + 0] = h0; hi[i + 1] = h1; hi[i + 2] = h2; hi[i + 3] = h3;
    lo[i + 0] = __float2bfloat16_rn(v.x - __bfloat162float(h0));
    lo[i + 1] = __float2bfloat16_rn(v.y - __bfloat162float(h1));
    lo[i + 2] = __float2bfloat16_rn(v.z - __bfloat162float(h2));
    lo[i + 3] = __float2bfloat16_rn(v.w - __bfloat162float(h3));
}

// ---------------------------------------------------------------------------
// MMA / async-copy primitives
// ---------------------------------------------------------------------------
__device__ __forceinline__ void ldsm4(uint32_t& r0, uint32_t& r1,
                                      uint32_t& r2, uint32_t& r3, uint32_t addr)
{
    asm volatile("ldmatrix.sync.aligned.m8n8.x4.shared.b16 {%0,%1,%2,%3}, [%4];"
                 : "=r"(r0), "=r"(r1), "=r"(r2), "=r"(r3) : "r"(addr));
}

__device__ __forceinline__ void mma_bf16(float& c0, float& c1, float& c2, float& c3,
                                         uint32_t a0, uint32_t a1, uint32_t a2, uint32_t a3,
                                         uint32_t b0, uint32_t b1)
{
    asm volatile(
        "mma.sync.aligned.m16n8k16.row.col.f32.bf16.bf16.f32 "
        "{%0,%1,%2,%3},{%4,%5,%6,%7},{%8,%9},{%0,%1,%2,%3};"
        : "+f"(c0), "+f"(c1), "+f"(c2), "+f"(c3)
        : "r"(a0), "r"(a1), "r"(a2), "r"(a3), "r"(b0), "r"(b1));
}

__device__ __forceinline__ void cp16(void* smem, const void* gmem)
{
    uint32_t s = (uint32_t)__cvta_generic_to_shared(smem);
    asm volatile("cp.async.cg.shared.global [%0], [%1], 16;" :: "r"(s), "l"(gmem));
}
__device__ __forceinline__ void cp_commit()
{
    asm volatile("cp.async.commit_group;");
}
__device__ __forceinline__ void cp_wait_all()
{
    asm volatile("cp.async.wait_group 0;");
}

// ---------------------------------------------------------------------------
// split-bf16 tensor-core GEMM, cp.async double-buffered.
// C[M,N] = A[M,K] @ B[N,K]^T (fp32 result)
// ---------------------------------------------------------------------------
#define GBM 128
#define GBN 128
#define GBK 32
#define ASTR 40
#define STAGE_ELEMS (4 * GBM * ASTR)            // Ah|Al|Bh|Bl, 20480 bf16
#define GEMM_SMEM (2 * STAGE_ELEMS * 2)         // 81920 B

__device__ __forceinline__ void gemm_load_stage(
    __nv_bfloat16* st,
    const __nv_bfloat16* __restrict__ Ah, const __nv_bfloat16* __restrict__ Al,
    const __nv_bfloat16* __restrict__ Bh, const __nv_bfloat16* __restrict__ Bl,
    int m0, int n0, int k0, int K, int tid)
{
#pragma unroll
    for (int p = 0; p < 2; ++p) {
        int idx = tid + p * 256;
        int row = idx >> 2;
        int cc = (idx & 3) * 8;
        cp16(&st[row * ASTR + cc],                 &Ah[(size_t)(m0 + row) * K + k0 + cc]);
        cp16(&st[GBM * ASTR + row * ASTR + cc],    &Al[(size_t)(m0 + row) * K + k0 + cc]);
        cp16(&st[2 * GBM * ASTR + row * ASTR + cc], &Bh[(size_t)(n0 + row) * K + k0 + cc]);
        cp16(&st[3 * GBM * ASTR + row * ASTR + cc], &Bl[(size_t)(n0 + row) * K + k0 + cc]);
    }
}

__global__ __launch_bounds__(256) void gemm_split(
    const __nv_bfloat16* __restrict__ Ah, const __nv_bfloat16* __restrict__ Al,
    const __nv_bfloat16* __restrict__ Bh, const __nv_bfloat16* __restrict__ Bl,
    float* __restrict__ C, int M, int N, int K)
{
    extern __shared__ char dynsm[];
    __nv_bfloat16* buf = (__nv_bfloat16*)dynsm;

    int tid = threadIdx.x;
    int lane = tid & 31;
    int w = tid >> 5;
    int wm = w & 1;
    int wn = w >> 1;
    int m0 = blockIdx.y * GBM;
    int n0 = blockIdx.x * GBN;

    float c[4][4][4] = {};

    int g = lane >> 3, r8 = lane & 7;
    int a_row_off = (g & 1) * 8;
    int a_k_off = (g >> 1) * 8;
    int b_n_off = (g >> 1) * 8;
    int b_k_off = (g & 1) * 8;

    gemm_load_stage(buf, Ah, Al, Bh, Bl, m0, n0, 0, K, tid);
    cp_commit();

    int p = 0;
    for (int k0 = 0; k0 < K; k0 += GBK) {
        cp_wait_all();
        __syncthreads();
        if (k0 + GBK < K) {
            gemm_load_stage(buf + (p ^ 1) * STAGE_ELEMS, Ah, Al, Bh, Bl,
                            m0, n0, k0 + GBK, K, tid);
            cp_commit();
        }
        __nv_bfloat16* sAh = buf + p * STAGE_ELEMS;
        __nv_bfloat16* sAl = sAh + GBM * ASTR;
        __nv_bfloat16* sBh = sAl + GBM * ASTR;
        __nv_bfloat16* sBl = sBh + GBM * ASTR;

#pragma unroll
        for (int ks = 0; ks < GBK; ks += 16) {
            uint32_t ah[4][4], al[4][4], bh[4][2], bl[4][2];
#pragma unroll
            for (int mt = 0; mt < 4; ++mt) {
                int roff = (wm * 64 + mt * 16 + a_row_off + r8) * ASTR + ks + a_k_off;
                ldsm4(ah[mt][0], ah[mt][1], ah[mt][2], ah[mt][3],
                      (uint32_t)__cvta_generic_to_shared(&sAh[roff]));
                ldsm4(al[mt][0], al[mt][1], al[mt][2], al[mt][3],
                      (uint32_t)__cvta_generic_to_shared(&sAl[roff]));
            }
#pragma unroll
            for (int ntp = 0; ntp < 2; ++ntp) {
                int roff = (wn * 32 + ntp * 16 + b_n_off + r8) * ASTR + ks + b_k_off;
                ldsm4(bh[ntp * 2][0], bh[ntp * 2][1], bh[ntp * 2 + 1][0], bh[ntp * 2 + 1][1],
                      (uint32_t)__cvta_generic_to_shared(&sBh[roff]));
                ldsm4(bl[ntp * 2][0], bl[ntp * 2][1], bl[ntp * 2 + 1][0], bl[ntp * 2 + 1][1],
                      (uint32_t)__cvta_generic_to_shared(&sBl[roff]));
            }
#pragma unroll
            for (int mt = 0; mt < 4; ++mt)
#pragma unroll
                for (int nt = 0; nt < 4; ++nt) {
                    float* cc = c[mt][nt];
                    mma_bf16(cc[0], cc[1], cc[2], cc[3],
                             ah[mt][0], ah[mt][1], ah[mt][2], ah[mt][3],
                             bh[nt][0], bh[nt][1]);
                    mma_bf16(cc[0], cc[1], cc[2], cc[3],
                             ah[mt][0], ah[mt][1], ah[mt][2], ah[mt][3],
                             bl[nt][0], bl[nt][1]);
                    mma_bf16(cc[0], cc[1], cc[2], cc[3],
                             al[mt][0], al[mt][1], al[mt][2], al[mt][3],
                             bh[nt][0], bh[nt][1]);
                }
        }
        p ^= 1;
    }

#pragma unroll
    for (int mt = 0; mt < 4; ++mt) {
#pragma unroll
        for (int nt = 0; nt < 4; ++nt) {
            int row = m0 + wm * 64 + mt * 16 + (lane >> 2);
            int col = n0 + wn * 32 + nt * 8 + 2 * (lane & 3);
            float* cc = c[mt][nt];
            *(float2*)&C[(size_t)row * N + col] = make_float2(cc[0], cc[1]);
            *(float2*)&C[(size_t)(row + 8) * N + col] = make_float2(cc[2], cc[3]);
        }
    }
}

// ---------------------------------------------------------------------------
// Fused RMSNorm + RoPE; emits split bf16 (hi,lo). grid (S, H, 2), block 128.
// ---------------------------------------------------------------------------
__global__ void rmsnorm_rope_split(
    const float* __restrict__ q, const float* __restrict__ k,
    const float* __restrict__ qw, const float* __restrict__ kw,
    const float* __restrict__ cosd, const float* __restrict__ sind,
    __nv_bfloat16* __restrict__ qh, __nv_bfloat16* __restrict__ ql,
    __nv_bfloat16* __restrict__ kh, __nv_bfloat16* __restrict__ kl)
{
    int s = blockIdx.x;
    int h = blockIdx.y;
    int which = blockIdx.z;
    int d = threadIdx.x;

    const float* buf = which ? k : q;
    const float* w = which ? kw : qw;
    __nv_bfloat16* oh = which ? kh : qh;
    __nv_bfloat16* ol = which ? kl : ql;
    const float* x = buf + (size_t)s * DIM + h * HD;

    float xd = x[d];
    int p = d ^ 64;
    float xp = x[p];

    float v = xd * xd;
#pragma unroll
    for (int off = 16; off; off >>= 1)
        v += __shfl_xor_sync(0xffffffffu, v, off);
    __shared__ float red[4];
    if ((d & 31) == 0) red[d >> 5] = v;
    __syncthreads();
    float var = (red[0] + red[1] + red[2] + red[3]) * (1.0f / HD);
    float rs = rsqrtf(var + EPSV);

    float xnd = xd * rs * (1.0f + w[d]);
    float xnp = xp * rs * (1.0f + w[p]);
    float c = cosd[(size_t)s * HD + d];
    float si = sind[(size_t)s * HD + d];
    float rot = (d < 64) ? -xnp : xnp;
    float outv = xnd * c + rot * si;

    size_t idx = (size_t)s * DIM + h * HD + d;
    __nv_bfloat16 hh = __float2bfloat16_rn(outv);
    oh[idx] = hh;
    ol[idx] = __float2bfloat16_rn(outv - __bfloat162float(hh));
}

// ---------------------------------------------------------------------------
// V transpose + split
// ---------------------------------------------------------------------------
__global__ void vt_split(const float* __restrict__ v,
                         __nv_bfloat16* __restrict__ vth,
                         __nv_bfloat16* __restrict__ vtl)
{
    __shared__ float tile[32][33];
    int d0 = blockIdx.x * 32;
    int s0 = blockIdx.y * 32;
    int tx = threadIdx.x, ty = threadIdx.y;
#pragma unroll
    for (int i = 0; i < 4; ++i) {
        int s = s0 + ty + i * 8;
        tile[ty + i * 8][tx] = v[(size_t)s * DIM + d0 + tx];
    }
    __syncthreads();
#pragma unroll
    for (int i = 0; i < 4; ++i) {
        int d = d0 + ty + i * 8;
        int s = s0 + tx;
        float val = tile[tx][ty + i * 8];
        __nv_bfloat16 hh = __float2bfloat16_rn(val);
        vth[(size_t)d * SEQ + s] = hh;
        vtl[(size_t)d * SEQ + s] = __float2bfloat16_rn(val - __bfloat162float(hh));
    }
}

// ---------------------------------------------------------------------------
// Windowed attention, tensor-core version (round-5, unchanged).
// ---------------------------------------------------------------------------
#define QBLK 64
#define KT 64
#define NTILE 9
#define SLABW 580
#define QKSTR 136
#define PSTR 72

#define ATT_A_OFF (QBLK * SLABW * 4)
#define ATT_B_OFF (ATT_A_OFF + 2 * QBLK * QKSTR * 2)
#define ATT_SMEM  (ATT_B_OFF + 2 * HD * PSTR * 2)

__global__ __launch_bounds__(256) void attn_kernel(
    const __nv_bfloat16* __restrict__ gqh, const __nv_bfloat16* __restrict__ gql,
    const __nv_bfloat16* __restrict__ gkh, const __nv_bfloat16* __restrict__ gkl,
    const __nv_bfloat16* __restrict__ gvth, const __nv_bfloat16* __restrict__ gvtl,
    float* __restrict__ probs, float* __restrict__ attn)
{
    extern __shared__ char smc[];
    float* slab = (float*)smc;
    __nv_bfloat16* Qh = (__nv_bfloat16*)(smc + ATT_A_OFF);
    __nv_bfloat16* Ql = Qh + QBLK * QKSTR;
    __nv_bfloat16* Ph = (__nv_bfloat16*)(smc + ATT_A_OFF);
    __nv_bfloat16* Pl = Ph + QBLK * PSTR;
    __nv_bfloat16* Kh = (__nv_bfloat16*)(smc + ATT_B_OFF);
    __nv_bfloat16* Kl = Kh + QBLK * QKSTR;
    __nv_bfloat16* Vh = (__nv_bfloat16*)(smc + ATT_B_OFF);
    __nv_bfloat16* Vl = Vh + HD * PSTR;
    __shared__ float rowscale[QBLK];

    int qb0 = blockIdx.x * QBLK;
    int h = blockIdx.y;
    int tid = threadIdx.x;
    int lane = tid & 31;
    int w = tid >> 5;
    int wm = w & 3;
    int wn = w >> 2;
    int kbase = qb0 - WIN;
    int t_start = (qb0 >= WIN) ? 0 : (WIN - qb0) / KT;
    int c0 = t_start * KT;

    int g = lane >> 3, r8 = lane & 7;
    int a_row_off = (g & 1) * 8;
    int a_k_off = (g >> 1) * 8;
    int b_n_off = (g >> 1) * 8;
    int b_k_off = (g & 1) * 8;
    int qg = lane >> 2, t4 = lane & 3;

#pragma unroll
    for (int i = 0; i < 4; ++i) {
        int idx = tid + i * 256;
        int row = idx >> 4;
        int c8 = (idx & 15) * 8;
        size_t goff = (size_t)(qb0 + row) * DIM + h * HD + c8;
        *(uint4*)&Qh[row * QKSTR + c8] = *(const uint4*)&gqh[goff];
        *(uint4*)&Ql[row * QKSTR + c8] = *(const uint4*)&gql[goff];
    }

    for (int t = t_start; t < NTILE; ++t) {
        __syncthreads();
#pragma unroll
        for (int i = 0; i < 4; ++i) {
            int idx = tid + i * 256;
            int row = idx >> 4;
            int c8 = (idx & 15) * 8;
            size_t goff = (size_t)(kbase + t * KT + row) * DIM + h * HD + c8;
            *(uint4*)&Kh[row * QKSTR + c8] = *(const uint4*)&gkh[goff];
            *(uint4*)&Kl[row * QKSTR + c8] = *(const uint4*)&gkl[goff];
        }
        __syncthreads();

        float acc[4][4] = {};
#pragma unroll
        for (int ks = 0; ks < 8; ++ks) {
            uint32_t qhf[4], qlf[4], bhf[4][2], blf[4][2];
            int aoff = (wm * 16 + a_row_off + r8) * QKSTR + ks * 16 + a_k_off;
            ldsm4(qhf[0], qhf[1], qhf[2], qhf[3],
                  (uint32_t)__cvta_generic_to_shared(&Qh[aoff]));
            ldsm4(qlf[0], qlf[1], qlf[2], qlf[3],
                  (uint32_t)__cvta_generic_to_shared(&Ql[aoff]));
#pragma unroll
            for (int ntp = 0; ntp < 2; ++ntp) {
                int boff = (wn * 32 + ntp * 16 + b_n_off + r8) * QKSTR + ks * 16 + b_k_off;
                ldsm4(bhf[ntp * 2][0], bhf[ntp * 2][1],
                      bhf[ntp * 2 + 1][0], bhf[ntp * 2 + 1][1],
                      (uint32_t)__cvta_generic_to_shared(&Kh[boff]));
                ldsm4(blf[ntp * 2][0], blf[ntp * 2][1],
                      blf[ntp * 2 + 1][0], blf[ntp * 2 + 1][1],
                      (uint32_t)__cvta_generic_to_shared(&Kl[boff]));
            }
#pragma unroll
            for (int nt = 0; nt < 4; ++nt) {
                float* cc = acc[nt];
                mma_bf16(cc[0], cc[1], cc[2], cc[3],
                         qhf[0], qhf[1], qhf[2], qhf[3], bhf[nt][0], bhf[nt][1]);
                mma_bf16(cc[0], cc[1], cc[2], cc[3],
                         qhf[0], qhf[1], qhf[2], qhf[3], blf[nt][0], blf[nt][1]);
                mma_bf16(cc[0], cc[1], cc[2], cc[3],
                         qlf[0], qlf[1], qlf[2], qlf[3], bhf[nt][0], bhf[nt][1]);
            }
        }

#pragma unroll
        for (int nt = 0; nt < 4; ++nt) {
#pragma unroll
            for (int e = 0; e < 4; ++e) {
                int r = wm * 16 + qg + (e >> 1) * 8;
                int cw = wn * 32 + nt * 8 + 2 * t4 + (e & 1);
                int qi = qb0 + r;
                int kj = kbase + t * KT + cw;
                float x = acc[nt][e] * (SCALING / SOFTCAP);
                float ex = __expf(2.0f * x);
                float sv = SOFTCAP * __fdividef(ex - 1.0f, ex + 1.0f);
                bool ok = (kj <= qi) && (qi - kj < WIN);
                slab[r * SLABW + t * KT + cw] = ok ? sv : NEGV;
            }
        }
    }
    __syncthreads();

    for (int r = w * 8; r < w * 8 + 8; ++r) {
        float m = NEGV;
        for (int c = c0 + lane; c < NTILE * KT; c += 32)
            m = fmaxf(m, slab[r * SLABW + c]);
#pragma unroll
        for (int off = 16; off; off >>= 1)
            m = fmaxf(m, __shfl_xor_sync(0xffffffffu, m, off));
        float ssum = 0.0f;
        for (int c = c0 + lane; c < NTILE * KT; c += 32) {
            float e = __expf(slab[r * SLABW + c] - m);
            slab[r * SLABW + c] = e;
            ssum += e;
        }
#pragma unroll
        for (int off = 16; off; off >>= 1)
            ssum += __shfl_xor_sync(0xffffffffu, ssum, off);
        if (lane == 0) rowscale[r] = 1.0f / ssum;
    }
    __syncthreads();

    for (int f = tid; f < QBLK * (NTILE * KT / 4); f += 256) {
        int row = f / (NTILE * KT / 4);
        int col = (f % (NTILE * KT / 4)) * 4;
        if (col < c0) continue;
        int j = kbase + col;
        float sc = rowscale[row];
        float4 e = *(const float4*)&slab[row * SLABW + col];
        float4 o = make_float4(e.x * sc, e.y * sc, e.z * sc, e.w * sc);
        *(float4*)&probs[(size_t)h * SEQ * SEQ + (size_t)(qb0 + row) * SEQ + j] = o;
    }

    float oacc[8][4] = {};
    for (int t = t_start; t < NTILE; ++t) {
        __syncthreads();
#pragma unroll
        for (int i = 0; i < 4; ++i) {
            int idx = tid + i * 256;
            int row = idx >> 4;
            int c4 = (idx & 15) * 4;
            float4 p = *(const float4*)&slab[row * SLABW + t * KT + c4];
            __nv_bfloat16 h0 = __float2bfloat16_rn(p.x);
            __nv_bfloat16 h1 = __float2bfloat16_rn(p.y);
            __nv_bfloat16 h2 = __float2bfloat16_rn(p.z);
            __nv_bfloat16 h3 = __float2bfloat16_rn(p.w);
            Ph[row * PSTR + c4 + 0] = h0;
            Ph[row * PSTR + c4 + 1] = h1;
            Ph[row * PSTR + c4 + 2] = h2;
            Ph[row * PSTR + c4 + 3] = h3;
            Pl[row * PSTR + c4 + 0] = __float2bfloat16_rn(p.x - __bfloat162float(h0));
            Pl[row * PSTR + c4 + 1] = __float2bfloat16_rn(p.y - __bfloat162float(h1));
            Pl[row * PSTR + c4 + 2] = __float2bfloat16_rn(p.z - __bfloat162float(h2));
            Pl[row * PSTR + c4 + 3] = __float2bfloat16_rn(p.w - __bfloat162float(h3));
        }
        int kstart = kbase + t * KT;
#pragma unroll
        for (int i = 0; i < 4; ++i) {
            int idx = tid + i * 256;
            int row = idx >> 3;
            int c8 = (idx & 7) * 8;
            size_t goff = (size_t)(h * HD + row) * SEQ + kstart + c8;
            *(uint4*)&Vh[row * PSTR + c8] = *(const uint4*)&gvth[goff];
            *(uint4*)&Vl[row * PSTR + c8] = *(const uint4*)&gvtl[goff];
        }
        __syncthreads();

#pragma unroll
        for (int ks = 0; ks < 4; ++ks) {
            uint32_t phf[4], plf[4], vhf[8][2], vlf[8][2];
            int aoff = (wm * 16 + a_row_off + r8) * PSTR + ks * 16 + a_k_off;
            ldsm4(phf[0], phf[1], phf[2], phf[3],
                  (uint32_t)__cvta_generic_to_shared(&Ph[aoff]));
            ldsm4(plf[0], plf[1], plf[2], plf[3],
                  (uint32_t)__cvta_generic_to_shared(&Pl[aoff]));
#pragma unroll
            for (int ntp = 0; ntp < 4; ++ntp) {
                int boff = (wn * 64 + ntp * 16 + b_n_off + r8) * PSTR + ks * 16 + b_k_off;
                ldsm4(vhf[ntp * 2][0], vhf[ntp * 2][1],
                      vhf[ntp * 2 + 1][0], vhf[ntp * 2 + 1][1],
                      (uint32_t)__cvta_generic_to_shared(&Vh[boff]));
                ldsm4(vlf[ntp * 2][0], vlf[ntp * 2][1],
                      vlf[ntp * 2 + 1][0], vlf[ntp * 2 + 1][1],
                      (uint32_t)__cvta_generic_to_shared(&Vl[boff]));
            }
#pragma unroll
            for (int nt = 0; nt < 8; ++nt) {
                float* cc = oacc[nt];
                mma_bf16(cc[0], cc[1], cc[2], cc[3],
                         phf[0], phf[1], phf[2], phf[3], vhf[nt][0], vhf[nt][1]);
                mma_bf16(cc[0], cc[1], cc[2], cc[3],
                         phf[0], phf[1], phf[2], phf[3], vlf[nt][0], vlf[nt][1]);
                mma_bf16(cc[0], cc[1], cc[2], cc[3],
                         plf[0], plf[1], plf[2], plf[3], vhf[nt][0], vhf[nt][1]);
            }
        }
    }

    {
        int r0 = wm * 16 + qg;
        int r1 = r0 + 8;
        float sc0 = rowscale[r0];
        float sc1 = rowscale[r1];
#pragma unroll
        for (int nt = 0; nt < 8; ++nt) {
            int col = wn * 64 + nt * 8 + 2 * t4;
            float* cc = oacc[nt];
            *(float2*)&attn[(size_t)(qb0 + r0) * DIM + h * HD + col] =
                make_float2(cc[0] * sc0, cc[1] * sc0);
            *(float2*)&attn[(size_t)(qb0 + r1) * DIM + h * HD + col] =
                make_float2(cc[2] * sc1, cc[3] * sc1);
        }
    }
}

// ---------------------------------------------------------------------------
extern "C" void kernel_launch(void* const* d_in, const int* in_sizes, int n_in,
                              void* d_out, int out_size)
{
    (void)in_sizes; (void)n_in; (void)out_size;
    const float* hidden = (const float*)d_in[0];
    const float* cosd   = (const float*)d_in[1];
    const float* sind   = (const float*)d_in[2];
    const float* Wq     = (const float*)d_in[3];
    const float* Wk     = (const float*)d_in[4];
    const float* Wv     = (const float*)d_in[5];
    const float* Wo     = (const float*)d_in[6];
    const float* qw     = (const float*)d_in[7];
    const float* kw     = (const float*)d_in[8];

    float* out = (float*)d_out;
    float* probs = out + (size_t)SEQ * DIM;

    float *qp, *kp, *vp, *ap;
    cudaGetSymbolAddress((void**)&qp, g_q);
    cudaGetSymbolAddress((void**)&kp, g_k);
    cudaGetSymbolAddress((void**)&vp, g_v);
    cudaGetSymbolAddress((void**)&ap, g_attn);
    __nv_bfloat16 *ah, *al, *wh, *wl, *qh, *ql, *kh, *kl, *vth, *vtl;
    cudaGetSymbolAddress((void**)&ah, g_ah);
    cudaGetSymbolAddress((void**)&al, g_al);
    cudaGetSymbolAddress((void**)&wh, g_wh);
    cudaGetSymbolAddress((void**)&wl, g_wl);
    cudaGetSymbolAddress((void**)&qh, g_qh);
    cudaGetSymbolAddress((void**)&ql, g_ql);
    cudaGetSymbolAddress((void**)&kh, g_kh);
    cudaGetSymbolAddress((void**)&kl, g_kl);
    cudaGetSymbolAddress((void**)&vth, g_vth);
    cudaGetSymbolAddress((void**)&vtl, g_vtl);

    // lazy one-time resources (created on first, non-capturing, call)
    static cudaStream_t s2 = nullptr;
    static cudaEvent_t ev_fork = nullptr, ev_join = nullptr;
    static bool smem_set = false;
    if (!s2) {
        cudaStreamCreateWithFlags(&s2, cudaStreamNonBlocking);
        cudaEventCreateWithFlags(&ev_fork, cudaEventDisableTiming);
        cudaEventCreateWithFlags(&ev_join, cudaEventDisableTiming);
    }
    if (!smem_set) {
        cudaFuncSetAttribute(gemm_split,
                             cudaFuncAttributeMaxDynamicSharedMemorySize, GEMM_SMEM);
        cudaFuncSetAttribute(attn_kernel,
                             cudaFuncAttributeMaxDynamicSharedMemorySize, ATT_SMEM);
        smem_set = true;
    }

    // fork: memset probs on side stream, overlapping the GEMMs
    cudaEventRecord(ev_fork, 0);
    cudaStreamWaitEvent(s2, ev_fork, 0);
    cudaMemsetAsync(probs, 0, (size_t)NH * SEQ * SEQ * sizeof(float), s2);
    cudaEventRecord(ev_join, s2);

    const int NELEM_A = SEQ * DIM, NELEM_W = DIM * DIM;
    dim3 ggemm(DIM / GBN, SEQ / GBM);

    split_kernel<<<NELEM_A / 4 / 256, 256>>>(hidden, ah, al, NELEM_A);

    split_kernel<<<NELEM_W / 4 / 256, 256>>>(Wq, wh, wl, NELEM_W);
    gemm_split<<<ggemm, 256, GEMM_SMEM>>>(ah, al, wh, wl, qp, SEQ, DIM, DIM);
    split_kernel<<<NELEM_W / 4 / 256, 256>>>(Wk, wh, wl, NELEM_W);
    gemm_split<<<ggemm, 256, GEMM_SMEM>>>(ah, al, wh, wl, kp, SEQ, DIM, DIM);
    split_kernel<<<NELEM_W / 4 / 256, 256>>>(Wv, wh, wl, NELEM_W);
    gemm_split<<<ggemm, 256, GEMM_SMEM>>>(ah, al, wh, wl, vp, SEQ, DIM, DIM);

    rmsnorm_rope_split<<<dim3(SEQ, NH, 2), HD>>>(qp, kp, qw, kw, cosd, sind,
                                                 qh, ql, kh, kl);
    vt_split<<<dim3(DIM / 32, SEQ / 32), dim3(32, 8)>>>(vp, vth, vtl);

    // join: probs memset must complete before band writes
    cudaStreamWaitEvent(0, ev_join, 0);

    attn_kernel<<<dim3(SEQ / QBLK, NH), 256, ATT_SMEM>>>(qh, ql, kh, kl, vth, vtl,
                                                         probs, ap);

    split_kernel<<<NELEM_A / 4 / 256, 256>>>(ap, ah, al, NELEM_A);
    split_kernel<<<NELEM_W / 4 / 256, 256>>>(Wo, wh, wl, NELEM_W);
    gemm_split<<<ggemm, 256, GEMM_SMEM>>>(ah, al, wh, wl, out, SEQ, DIM, DIM);
}

// round 8
// speedup vs baseline: 2.5577x; 1.0816x over previous
#include <cuda_runtime.h>
#include <cuda_bf16.h>
#include <cstdint>
#include <cstddef>
#include <math.h>

#define SEQ 4096
#define DIM 1024
#define NH 8
#define HD 128
#define WIN 512
#define SCALING 0.0625f
#define SOFTCAP 50.0f
#define EPSV 1e-6f
#define NEGV -1e30f

// scratch (allocation-free rule: device globals)
__device__ float g_q[SEQ * DIM];
__device__ float g_k[SEQ * DIM];
__device__ float g_v[SEQ * DIM];
__device__ __align__(16) __nv_bfloat16 g_ah[SEQ * DIM];
__device__ __align__(16) __nv_bfloat16 g_al[SEQ * DIM];
__device__ __align__(16) __nv_bfloat16 g_wh[4 * DIM * DIM];
__device__ __align__(16) __nv_bfloat16 g_wl[4 * DIM * DIM];
__device__ __align__(16) __nv_bfloat16 g_qh[SEQ * DIM];
__device__ __align__(16) __nv_bfloat16 g_ql[SEQ * DIM];
__device__ __align__(16) __nv_bfloat16 g_kh[SEQ * DIM];
__device__ __align__(16) __nv_bfloat16 g_kl[SEQ * DIM];
__device__ __align__(16) __nv_bfloat16 g_vth[DIM * SEQ];
__device__ __align__(16) __nv_bfloat16 g_vtl[DIM * SEQ];

// ---------------------------------------------------------------------------
// fp32 -> (bf16 hi, bf16 lo) split
// ---------------------------------------------------------------------------
__global__ void split_kernel(const float* __restrict__ x,
                             __nv_bfloat16* __restrict__ hi,
                             __nv_bfloat16* __restrict__ lo, int n)
{
    int i = (blockIdx.x * blockDim.x + threadIdx.x) * 4;
    if (i >= n) return;
    float4 v = *(const float4*)&x[i];
    __nv_bfloat16 h0 = __float2bfloat16_rn(v.x);
    __nv_bfloat16 h1 = __float2bfloat16_rn(v.y);
    __nv_bfloat16 h2 = __float2bfloat16_rn(v.z);
    __nv_bfloat16 h3 = __float2bfloat16_rn(v.w);
    hi[i + 0] = h0; hi[i + 1] = h1; hi[i + 2] = h2; hi[i + 3] = h3;
    lo[i + 0] = __float2bfloat16_rn(v.x - __bfloat162float(h0));
    lo[i + 1] = __float2bfloat16_rn(v.y - __bfloat162float(h1));
    lo[i + 2] = __float2bfloat16_rn(v.z - __bfloat162float(h2));
    lo[i + 3] = __float2bfloat16_rn(v.w - __bfloat162float(h3));
}

// ---------------------------------------------------------------------------
// MMA / async-copy primitives
// ---------------------------------------------------------------------------
__device__ __forceinline__ void ldsm4(uint32_t& r0, uint32_t& r1,
                                      uint32_t& r2, uint32_t& r3, uint32_t addr)
{
    asm volatile("ldmatrix.sync.aligned.m8n8.x4.shared.b16 {%0,%1,%2,%3}, [%4];"
                 : "=r"(r0), "=r"(r1), "=r"(r2), "=r"(r3) : "r"(addr));
}

__device__ __forceinline__ void mma_bf16(float& c0, float& c1, float& c2, float& c3,
                                         uint32_t a0, uint32_t a1, uint32_t a2, uint32_t a3,
                                         uint32_t b0, uint32_t b1)
{
    asm volatile(
        "mma.sync.aligned.m16n8k16.row.col.f32.bf16.bf16.f32 "
        "{%0,%1,%2,%3},{%4,%5,%6,%7},{%8,%9},{%0,%1,%2,%3};"
        : "+f"(c0), "+f"(c1), "+f"(c2), "+f"(c3)
        : "r"(a0), "r"(a1), "r"(a2), "r"(a3), "r"(b0), "r"(b1));
}

__device__ __forceinline__ void cp16(void* smem, const void* gmem)
{
    uint32_t s = (uint32_t)__cvta_generic_to_shared(smem);
    asm volatile("cp.async.cg.shared.global [%0], [%1], 16;" :: "r"(s), "l"(gmem));
}
__device__ __forceinline__ void cp_commit()
{
    asm volatile("cp.async.commit_group;");
}
template <int N>
__device__ __forceinline__ void cp_wait()
{
    asm volatile("cp.async.wait_group %0;" :: "n"(N));
}

// ---------------------------------------------------------------------------
// split-bf16 tensor-core GEMM, cp.async double-buffered (round-6, proven).
// C[M,N] = A[M,K] @ B[N,K]^T (fp32 result)
// ---------------------------------------------------------------------------
#define GBM 128
#define GBN 128
#define GBK 32
#define ASTR 40
#define STAGE_ELEMS (4 * GBM * ASTR)
#define GEMM_SMEM (2 * STAGE_ELEMS * 2)

__device__ __forceinline__ void gemm_load_stage(
    __nv_bfloat16* st,
    const __nv_bfloat16* __restrict__ Ah, const __nv_bfloat16* __restrict__ Al,
    const __nv_bfloat16* __restrict__ Bh, const __nv_bfloat16* __restrict__ Bl,
    int m0, int n0, int k0, int K, int tid)
{
#pragma unroll
    for (int p = 0; p < 2; ++p) {
        int idx = tid + p * 256;
        int row = idx >> 2;
        int cc = (idx & 3) * 8;
        cp16(&st[row * ASTR + cc],                  &Ah[(size_t)(m0 + row) * K + k0 + cc]);
        cp16(&st[GBM * ASTR + row * ASTR + cc],     &Al[(size_t)(m0 + row) * K + k0 + cc]);
        cp16(&st[2 * GBM * ASTR + row * ASTR + cc], &Bh[(size_t)(n0 + row) * K + k0 + cc]);
        cp16(&st[3 * GBM * ASTR + row * ASTR + cc], &Bl[(size_t)(n0 + row) * K + k0 + cc]);
    }
}

__global__ __launch_bounds__(256) void gemm_split(
    const __nv_bfloat16* __restrict__ Ah, const __nv_bfloat16* __restrict__ Al,
    const __nv_bfloat16* __restrict__ Bh, const __nv_bfloat16* __restrict__ Bl,
    float* __restrict__ C, int M, int N, int K)
{
    extern __shared__ char dynsm[];
    __nv_bfloat16* buf = (__nv_bfloat16*)dynsm;

    int tid = threadIdx.x;
    int lane = tid & 31;
    int w = tid >> 5;
    int wm = w & 1;
    int wn = w >> 1;
    int m0 = blockIdx.y * GBM;
    int n0 = blockIdx.x * GBN;

    float c[4][4][4] = {};

    int g = lane >> 3, r8 = lane & 7;
    int a_row_off = (g & 1) * 8;
    int a_k_off = (g >> 1) * 8;
    int b_n_off = (g >> 1) * 8;
    int b_k_off = (g & 1) * 8;

    gemm_load_stage(buf, Ah, Al, Bh, Bl, m0, n0, 0, K, tid);
    cp_commit();

    int p = 0;
    for (int k0 = 0; k0 < K; k0 += GBK) {
        cp_wait<0>();
        __syncthreads();
        if (k0 + GBK < K) {
            gemm_load_stage(buf + (p ^ 1) * STAGE_ELEMS, Ah, Al, Bh, Bl,
                            m0, n0, k0 + GBK, K, tid);
            cp_commit();
        }
        __nv_bfloat16* sAh = buf + p * STAGE_ELEMS;
        __nv_bfloat16* sAl = sAh + GBM * ASTR;
        __nv_bfloat16* sBh = sAl + GBM * ASTR;
        __nv_bfloat16* sBl = sBh + GBM * ASTR;

#pragma unroll
        for (int ks = 0; ks < GBK; ks += 16) {
            uint32_t ah[4][4], al[4][4], bh[4][2], bl[4][2];
#pragma unroll
            for (int mt = 0; mt < 4; ++mt) {
                int roff = (wm * 64 + mt * 16 + a_row_off + r8) * ASTR + ks + a_k_off;
                ldsm4(ah[mt][0], ah[mt][1], ah[mt][2], ah[mt][3],
                      (uint32_t)__cvta_generic_to_shared(&sAh[roff]));
                ldsm4(al[mt][0], al[mt][1], al[mt][2], al[mt][3],
                      (uint32_t)__cvta_generic_to_shared(&sAl[roff]));
            }
#pragma unroll
            for (int ntp = 0; ntp < 2; ++ntp) {
                int roff = (wn * 32 + ntp * 16 + b_n_off + r8) * ASTR + ks + b_k_off;
                ldsm4(bh[ntp * 2][0], bh[ntp * 2][1], bh[ntp * 2 + 1][0], bh[ntp * 2 + 1][1],
                      (uint32_t)__cvta_generic_to_shared(&sBh[roff]));
                ldsm4(bl[ntp * 2][0], bl[ntp * 2][1], bl[ntp * 2 + 1][0], bl[ntp * 2 + 1][1],
                      (uint32_t)__cvta_generic_to_shared(&sBl[roff]));
            }
#pragma unroll
            for (int mt = 0; mt < 4; ++mt)
#pragma unroll
                for (int nt = 0; nt < 4; ++nt) {
                    float* cc = c[mt][nt];
                    mma_bf16(cc[0], cc[1], cc[2], cc[3],
                             ah[mt][0], ah[mt][1], ah[mt][2], ah[mt][3],
                             bh[nt][0], bh[nt][1]);
                    mma_bf16(cc[0], cc[1], cc[2], cc[3],
                             ah[mt][0], ah[mt][1], ah[mt][2], ah[mt][3],
                             bl[nt][0], bl[nt][1]);
                    mma_bf16(cc[0], cc[1], cc[2], cc[3],
                             al[mt][0], al[mt][1], al[mt][2], al[mt][3],
                             bh[nt][0], bh[nt][1]);
                }
        }
        p ^= 1;
    }

#pragma unroll
    for (int mt = 0; mt < 4; ++mt) {
#pragma unroll
        for (int nt = 0; nt < 4; ++nt) {
            int row = m0 + wm * 64 + mt * 16 + (lane >> 2);
            int col = n0 + wn * 32 + nt * 8 + 2 * (lane & 3);
            float* cc = c[mt][nt];
            *(float2*)&C[(size_t)row * N + col] = make_float2(cc[0], cc[1]);
            *(float2*)&C[(size_t)(row + 8) * N + col] = make_float2(cc[2], cc[3]);
        }
    }
}

// ---------------------------------------------------------------------------
// Fused RMSNorm + RoPE; emits split bf16 (hi,lo). grid (S, H, 2), block 128.
// ---------------------------------------------------------------------------
__global__ void rmsnorm_rope_split(
    const float* __restrict__ q, const float* __restrict__ k,
    const float* __restrict__ qw, const float* __restrict__ kw,
    const float* __restrict__ cosd, const float* __restrict__ sind,
    __nv_bfloat16* __restrict__ qh, __nv_bfloat16* __restrict__ ql,
    __nv_bfloat16* __restrict__ kh, __nv_bfloat16* __restrict__ kl)
{
    int s = blockIdx.x;
    int h = blockIdx.y;
    int which = blockIdx.z;
    int d = threadIdx.x;

    const float* buf = which ? k : q;
    const float* w = which ? kw : qw;
    __nv_bfloat16* oh = which ? kh : qh;
    __nv_bfloat16* ol = which ? kl : ql;
    const float* x = buf + (size_t)s * DIM + h * HD;

    float xd = x[d];
    int p = d ^ 64;
    float xp = x[p];

    float v = xd * xd;
#pragma unroll
    for (int off = 16; off; off >>= 1)
        v += __shfl_xor_sync(0xffffffffu, v, off);
    __shared__ float red[4];
    if ((d & 31) == 0) red[d >> 5] = v;
    __syncthreads();
    float var = (red[0] + red[1] + red[2] + red[3]) * (1.0f / HD);
    float rs = rsqrtf(var + EPSV);

    float xnd = xd * rs * (1.0f + w[d]);
    float xnp = xp * rs * (1.0f + w[p]);
    float c = cosd[(size_t)s * HD + d];
    float si = sind[(size_t)s * HD + d];
    float rot = (d < 64) ? -xnp : xnp;
    float outv = xnd * c + rot * si;

    size_t idx = (size_t)s * DIM + h * HD + d;
    __nv_bfloat16 hh = __float2bfloat16_rn(outv);
    oh[idx] = hh;
    ol[idx] = __float2bfloat16_rn(outv - __bfloat162float(hh));
}

// ---------------------------------------------------------------------------
// V transpose + split
// ---------------------------------------------------------------------------
__global__ void vt_split(const float* __restrict__ v,
                         __nv_bfloat16* __restrict__ vth,
                         __nv_bfloat16* __restrict__ vtl)
{
    __shared__ float tile[32][33];
    int d0 = blockIdx.x * 32;
    int s0 = blockIdx.y * 32;
    int tx = threadIdx.x, ty = threadIdx.y;
#pragma unroll
    for (int i = 0; i < 4; ++i) {
        int s = s0 + ty + i * 8;
        tile[ty + i * 8][tx] = v[(size_t)s * DIM + d0 + tx];
    }
    __syncthreads();
#pragma unroll
    for (int i = 0; i < 4; ++i) {
        int d = d0 + ty + i * 8;
        int s = s0 + tx;
        float val = tile[tx][ty + i * 8];
        __nv_bfloat16 hh = __float2bfloat16_rn(val);
        vth[(size_t)d * SEQ + s] = hh;
        vtl[(size_t)d * SEQ + s] = __float2bfloat16_rn(val - __bfloat162float(hh));
    }
}

// ---------------------------------------------------------------------------
// Windowed attention, tensor-core + register-staged prefetch.
// CTA = 64 queries x 1 head, 256 threads (8 warps). Emits split-bf16 O.
// ---------------------------------------------------------------------------
#define QBLK 64
#define KT 64
#define NTILE 9
#define SLABW 580
#define QKSTR 136
#define PSTR 72

#define ATT_A_OFF (QBLK * SLABW * 4)
#define ATT_B_OFF (ATT_A_OFF + 2 * QBLK * QKSTR * 2)
#define ATT_SMEM  (ATT_B_OFF + 2 * HD * PSTR * 2)

__global__ __launch_bounds__(256) void attn_kernel(
    const __nv_bfloat16* __restrict__ gqh, const __nv_bfloat16* __restrict__ gql,
    const __nv_bfloat16* __restrict__ gkh, const __nv_bfloat16* __restrict__ gkl,
    const __nv_bfloat16* __restrict__ gvth, const __nv_bfloat16* __restrict__ gvtl,
    float* __restrict__ probs,
    __nv_bfloat16* __restrict__ oh, __nv_bfloat16* __restrict__ ol)
{
    extern __shared__ char smc[];
    float* slab = (float*)smc;
    __nv_bfloat16* Qh = (__nv_bfloat16*)(smc + ATT_A_OFF);
    __nv_bfloat16* Ql = Qh + QBLK * QKSTR;
    __nv_bfloat16* Ph = (__nv_bfloat16*)(smc + ATT_A_OFF);
    __nv_bfloat16* Pl = Ph + QBLK * PSTR;
    __nv_bfloat16* Kh = (__nv_bfloat16*)(smc + ATT_B_OFF);
    __nv_bfloat16* Kl = Kh + QBLK * QKSTR;
    __nv_bfloat16* Vh = (__nv_bfloat16*)(smc + ATT_B_OFF);
    __nv_bfloat16* Vl = Vh + HD * PSTR;
    __shared__ float rowscale[QBLK];

    int qb0 = blockIdx.x * QBLK;
    int h = blockIdx.y;
    int tid = threadIdx.x;
    int lane = tid & 31;
    int w = tid >> 5;
    int wm = w & 3;
    int wn = w >> 2;
    int kbase = qb0 - WIN;
    int t_start = (qb0 >= WIN) ? 0 : (WIN - qb0) / KT;
    int c0 = t_start * KT;

    int g = lane >> 3, r8 = lane & 7;
    int a_row_off = (g & 1) * 8;
    int a_k_off = (g >> 1) * 8;
    int b_n_off = (g >> 1) * 8;
    int b_k_off = (g & 1) * 8;
    int qg = lane >> 2, t4 = lane & 3;

    // per-thread K-tile slice coords
    int krow = tid >> 4;             // 0..15 (x4 via +16*i)  -- wait: see below
    // (K tiles: 64 rows x 128 cols bf16; idx mapping row=idx>>4, c8=(idx&15)*8)

    // ---- load Q tiles (hi/lo) ----
#pragma unroll
    for (int i = 0; i < 4; ++i) {
        int idx = tid + i * 256;
        int row = idx >> 4;
        int c8 = (idx & 15) * 8;
        size_t goff = (size_t)(qb0 + row) * DIM + h * HD + c8;
        *(uint4*)&Qh[row * QKSTR + c8] = *(const uint4*)&gqh[goff];
        *(uint4*)&Ql[row * QKSTR + c8] = *(const uint4*)&gql[goff];
    }

    // ================= scores (register-staged prefetch) =================
    uint4 pkh[4], pkl[4];
    {
        int kstart = kbase + t_start * KT;
#pragma unroll
        for (int i = 0; i < 4; ++i) {
            int idx = tid + i * 256;
            int row = idx >> 4;
            int c8 = (idx & 15) * 8;
            size_t goff = (size_t)(kstart + row) * DIM + h * HD + c8;
            pkh[i] = *(const uint4*)&gkh[goff];
            pkl[i] = *(const uint4*)&gkl[goff];
        }
    }

    for (int t = t_start; t < NTILE; ++t) {
        __syncthreads();
#pragma unroll
        for (int i = 0; i < 4; ++i) {
            int idx = tid + i * 256;
            int row = idx >> 4;
            int c8 = (idx & 15) * 8;
            *(uint4*)&Kh[row * QKSTR + c8] = pkh[i];
            *(uint4*)&Kl[row * QKSTR + c8] = pkl[i];
        }
        __syncthreads();
        if (t + 1 < NTILE) {
            int kstart = kbase + (t + 1) * KT;
#pragma unroll
            for (int i = 0; i < 4; ++i) {
                int idx = tid + i * 256;
                int row = idx >> 4;
                int c8 = (idx & 15) * 8;
                size_t goff = (size_t)(kstart + row) * DIM + h * HD + c8;
                pkh[i] = *(const uint4*)&gkh[goff];
                pkl[i] = *(const uint4*)&gkl[goff];
            }
        }

        float acc[4][4] = {};
#pragma unroll
        for (int ks = 0; ks < 8; ++ks) {
            uint32_t qhf[4], qlf[4], bhf[4][2], blf[4][2];
            int aoff = (wm * 16 + a_row_off + r8) * QKSTR + ks * 16 + a_k_off;
            ldsm4(qhf[0], qhf[1], qhf[2], qhf[3],
                  (uint32_t)__cvta_generic_to_shared(&Qh[aoff]));
            ldsm4(qlf[0], qlf[1], qlf[2], qlf[3],
                  (uint32_t)__cvta_generic_to_shared(&Ql[aoff]));
#pragma unroll
            for (int ntp = 0; ntp < 2; ++ntp) {
                int boff = (wn * 32 + ntp * 16 + b_n_off + r8) * QKSTR + ks * 16 + b_k_off;
                ldsm4(bhf[ntp * 2][0], bhf[ntp * 2][1],
                      bhf[ntp * 2 + 1][0], bhf[ntp * 2 + 1][1],
                      (uint32_t)__cvta_generic_to_shared(&Kh[boff]));
                ldsm4(blf[ntp * 2][0], blf[ntp * 2][1],
                      blf[ntp * 2 + 1][0], blf[ntp * 2 + 1][1],
                      (uint32_t)__cvta_generic_to_shared(&Kl[boff]));
            }
#pragma unroll
            for (int nt = 0; nt < 4; ++nt) {
                float* cc = acc[nt];
                mma_bf16(cc[0], cc[1], cc[2], cc[3],
                         qhf[0], qhf[1], qhf[2], qhf[3], bhf[nt][0], bhf[nt][1]);
                mma_bf16(cc[0], cc[1], cc[2], cc[3],
                         qhf[0], qhf[1], qhf[2], qhf[3], blf[nt][0], blf[nt][1]);
                mma_bf16(cc[0], cc[1], cc[2], cc[3],
                         qlf[0], qlf[1], qlf[2], qlf[3], bhf[nt][0], bhf[nt][1]);
            }
        }

#pragma unroll
        for (int nt = 0; nt < 4; ++nt) {
#pragma unroll
            for (int e = 0; e < 4; ++e) {
                int r = wm * 16 + qg + (e >> 1) * 8;
                int cw = wn * 32 + nt * 8 + 2 * t4 + (e & 1);
                int qi = qb0 + r;
                int kj = kbase + t * KT + cw;
                float x = acc[nt][e] * (SCALING / SOFTCAP);
                float ex = __expf(2.0f * x);
                float sv = SOFTCAP * __fdividef(ex - 1.0f, ex + 1.0f);
                bool ok = (kj <= qi) && (qi - kj < WIN);
                slab[r * SLABW + t * KT + cw] = ok ? sv : NEGV;
            }
        }
    }
    __syncthreads();

    // ================= softmax (exact) =================
    for (int r = w * 8; r < w * 8 + 8; ++r) {
        float m = NEGV;
        for (int c = c0 + lane; c < NTILE * KT; c += 32)
            m = fmaxf(m, slab[r * SLABW + c]);
#pragma unroll
        for (int off = 16; off; off >>= 1)
            m = fmaxf(m, __shfl_xor_sync(0xffffffffu, m, off));
        float ssum = 0.0f;
        for (int c = c0 + lane; c < NTILE * KT; c += 32) {
            float e = __expf(slab[r * SLABW + c] - m);
            slab[r * SLABW + c] = e;
            ssum += e;
        }
#pragma unroll
        for (int off = 16; off; off >>= 1)
            ssum += __shfl_xor_sync(0xffffffffu, ssum, off);
        if (lane == 0) rowscale[r] = 1.0f / ssum;
    }
    __syncthreads();

    // ================= probs band write =================
    for (int f = tid; f < QBLK * (NTILE * KT / 4); f += 256) {
        int row = f / (NTILE * KT / 4);
        int col = (f % (NTILE * KT / 4)) * 4;
        if (col < c0) continue;
        int j = kbase + col;
        float sc = rowscale[row];
        float4 e = *(const float4*)&slab[row * SLABW + col];
        float4 o = make_float4(e.x * sc, e.y * sc, e.z * sc, e.w * sc);
        *(float4*)&probs[(size_t)h * SEQ * SEQ + (size_t)(qb0 + row) * SEQ + j] = o;
    }

    // ================= P @ V (register-staged prefetch) =================
    uint4 pvh[4], pvl[4];
    {
        int kstart = kbase + t_start * KT;
#pragma unroll
        for (int i = 0; i < 4; ++i) {
            int idx = tid + i * 256;
            int row = idx >> 3;
            int c8 = (idx & 7) * 8;
            size_t goff = (size_t)(h * HD + row) * SEQ + kstart + c8;
            pvh[i] = *(const uint4*)&gvth[goff];
            pvl[i] = *(const uint4*)&gvtl[goff];
        }
    }

    float oacc[8][4] = {};
    for (int t = t_start; t < NTILE; ++t) {
        __syncthreads();
        // convert P tile (exp values) -> split bf16
#pragma unroll
        for (int i = 0; i < 4; ++i) {
            int idx = tid + i * 256;
            int row = idx >> 4;
            int c4 = (idx & 15) * 4;
            float4 p = *(const float4*)&slab[row * SLABW + t * KT + c4];
            __nv_bfloat16 h0 = __float2bfloat16_rn(p.x);
            __nv_bfloat16 h1 = __float2bfloat16_rn(p.y);
            __nv_bfloat16 h2 = __float2bfloat16_rn(p.z);
            __nv_bfloat16 h3 = __float2bfloat16_rn(p.w);
            Ph[row * PSTR + c4 + 0] = h0;
            Ph[row * PSTR + c4 + 1] = h1;
            Ph[row * PSTR + c4 + 2] = h2;
            Ph[row * PSTR + c4 + 3] = h3;
            Pl[row * PSTR + c4 + 0] = __float2bfloat16_rn(p.x - __bfloat162float(h0));
            Pl[row * PSTR + c4 + 1] = __float2bfloat16_rn(p.y - __bfloat162float(h1));
            Pl[row * PSTR + c4 + 2] = __float2bfloat16_rn(p.z - __bfloat162float(h2));
            Pl[row * PSTR + c4 + 3] = __float2bfloat16_rn(p.w - __bfloat162float(h3));
        }
#pragma unroll
        for (int i = 0; i < 4; ++i) {
            int idx = tid + i * 256;
            int row = idx >> 3;
            int c8 = (idx & 7) * 8;
            *(uint4*)&Vh[row * PSTR + c8] = pvh[i];
            *(uint4*)&Vl[row * PSTR + c8] = pvl[i];
        }
        __syncthreads();
        if (t + 1 < NTILE) {
            int kstart = kbase + (t + 1) * KT;
#pragma unroll
            for (int i = 0; i < 4; ++i) {
                int idx = tid + i * 256;
                int row = idx >> 3;
                int c8 = (idx & 7) * 8;
                size_t goff = (size_t)(h * HD + row) * SEQ + kstart + c8;
                pvh[i] = *(const uint4*)&gvth[goff];
                pvl[i] = *(const uint4*)&gvtl[goff];
            }
        }

#pragma unroll
        for (int ks = 0; ks < 4; ++ks) {
            uint32_t phf[4], plf[4], vhf[8][2], vlf[8][2];
            int aoff = (wm * 16 + a_row_off + r8) * PSTR + ks * 16 + a_k_off;
            ldsm4(phf[0], phf[1], phf[2], phf[3],
                  (uint32_t)__cvta_generic_to_shared(&Ph[aoff]));
            ldsm4(plf[0], plf[1], plf[2], plf[3],
                  (uint32_t)__cvta_generic_to_shared(&Pl[aoff]));
#pragma unroll
            for (int ntp = 0; ntp < 4; ++ntp) {
                int boff = (wn * 64 + ntp * 16 + b_n_off + r8) * PSTR + ks * 16 + b_k_off;
                ldsm4(vhf[ntp * 2][0], vhf[ntp * 2][1],
                      vhf[ntp * 2 + 1][0], vhf[ntp * 2 + 1][1],
                      (uint32_t)__cvta_generic_to_shared(&Vh[boff]));
                ldsm4(vlf[ntp * 2][0], vlf[ntp * 2][1],
                      vlf[ntp * 2 + 1][0], vlf[ntp * 2 + 1][1],
                      (uint32_t)__cvta_generic_to_shared(&Vl[boff]));
            }
#pragma unroll
            for (int nt = 0; nt < 8; ++nt) {
                float* cc = oacc[nt];
                mma_bf16(cc[0], cc[1], cc[2], cc[3],
                         phf[0], phf[1], phf[2], phf[3], vhf[nt][0], vhf[nt][1]);
                mma_bf16(cc[0], cc[1], cc[2], cc[3],
                         phf[0], phf[1], phf[2], phf[3], vlf[nt][0], vlf[nt][1]);
                mma_bf16(cc[0], cc[1], cc[2], cc[3],
                         plf[0], plf[1], plf[2], plf[3], vhf[nt][0], vhf[nt][1]);
            }
        }
    }

    // ---- write O (scaled by 1/rowsum) as split bf16 ----
    {
        int r0 = wm * 16 + qg;
        int r1 = r0 + 8;
        float sc0 = rowscale[r0];
        float sc1 = rowscale[r1];
#pragma unroll
        for (int nt = 0; nt < 8; ++nt) {
            int col = wn * 64 + nt * 8 + 2 * t4;
            float* cc = oacc[nt];
            float f00 = cc[0] * sc0, f01 = cc[1] * sc0;
            float f10 = cc[2] * sc1, f11 = cc[3] * sc1;
            size_t o0 = (size_t)(qb0 + r0) * DIM + h * HD + col;
            size_t o1 = (size_t)(qb0 + r1) * DIM + h * HD + col;
            __nv_bfloat16 h00 = __float2bfloat16_rn(f00);
            __nv_bfloat16 h01 = __float2bfloat16_rn(f01);
            __nv_bfloat16 h10 = __float2bfloat16_rn(f10);
            __nv_bfloat16 h11 = __float2bfloat16_rn(f11);
            *(__nv_bfloat162*)&oh[o0] = __nv_bfloat162(h00, h01);
            *(__nv_bfloat162*)&oh[o1] = __nv_bfloat162(h10, h11);
            *(__nv_bfloat162*)&ol[o0] = __nv_bfloat162(
                __float2bfloat16_rn(f00 - __bfloat162float(h00)),
                __float2bfloat16_rn(f01 - __bfloat162float(h01)));
            *(__nv_bfloat162*)&ol[o1] = __nv_bfloat162(
                __float2bfloat16_rn(f10 - __bfloat162float(h10)),
                __float2bfloat16_rn(f11 - __bfloat162float(h11)));
        }
    }
}

// ---------------------------------------------------------------------------
extern "C" void kernel_launch(void* const* d_in, const int* in_sizes, int n_in,
                              void* d_out, int out_size)
{
    (void)in_sizes; (void)n_in; (void)out_size;
    const float* hidden = (const float*)d_in[0];
    const float* cosd   = (const float*)d_in[1];
    const float* sind   = (const float*)d_in[2];
    const float* Wq     = (const float*)d_in[3];
    const float* Wk     = (const float*)d_in[4];
    const float* Wv     = (const float*)d_in[5];
    const float* Wo     = (const float*)d_in[6];
    const float* qw     = (const float*)d_in[7];
    const float* kw     = (const float*)d_in[8];

    float* out = (float*)d_out;
    float* probs = out + (size_t)SEQ * DIM;

    float *qp, *kp, *vp;
    cudaGetSymbolAddress((void**)&qp, g_q);
    cudaGetSymbolAddress((void**)&kp, g_k);
    cudaGetSymbolAddress((void**)&vp, g_v);
    __nv_bfloat16 *ah, *al, *wh, *wl, *qh, *ql, *kh, *kl, *vth, *vtl;
    cudaGetSymbolAddress((void**)&ah, g_ah);
    cudaGetSymbolAddress((void**)&al, g_al);
    cudaGetSymbolAddress((void**)&wh, g_wh);
    cudaGetSymbolAddress((void**)&wl, g_wl);
    cudaGetSymbolAddress((void**)&qh, g_qh);
    cudaGetSymbolAddress((void**)&ql, g_ql);
    cudaGetSymbolAddress((void**)&kh, g_kh);
    cudaGetSymbolAddress((void**)&kl, g_kl);
    cudaGetSymbolAddress((void**)&vth, g_vth);
    cudaGetSymbolAddress((void**)&vtl, g_vtl);

    // lazy one-time resources (created on first, non-capturing, call)
    static cudaStream_t s2 = nullptr;
    static cudaEvent_t ev_fork = nullptr, ev_join = nullptr;
    static cudaEvent_t ev_gemmv = nullptr, ev_vt = nullptr;
    static bool smem_set = false;
    if (!s2) {
        cudaStreamCreateWithFlags(&s2, cudaStreamNonBlocking);
        cudaEventCreateWithFlags(&ev_fork, cudaEventDisableTiming);
        cudaEventCreateWithFlags(&ev_join, cudaEventDisableTiming);
        cudaEventCreateWithFlags(&ev_gemmv, cudaEventDisableTiming);
        cudaEventCreateWithFlags(&ev_vt, cudaEventDisableTiming);
    }
    if (!smem_set) {
        cudaFuncSetAttribute(gemm_split,
                             cudaFuncAttributeMaxDynamicSharedMemorySize, GEMM_SMEM);
        cudaFuncSetAttribute(attn_kernel,
                             cudaFuncAttributeMaxDynamicSharedMemorySize, ATT_SMEM);
        smem_set = true;
    }

    // fork: memset probs on side stream, overlapping the GEMMs
    cudaEventRecord(ev_fork, 0);
    cudaStreamWaitEvent(s2, ev_fork, 0);
    cudaMemsetAsync(probs, 0, (size_t)NH * SEQ * SEQ * sizeof(float), s2);
    cudaEventRecord(ev_join, s2);

    const int NELEM_A = SEQ * DIM, NELEM_W = DIM * DIM;
    dim3 ggemm(DIM / GBN, SEQ / GBM);

    // all splits upfront
    split_kernel<<<NELEM_A / 4 / 256, 256>>>(hidden, ah, al, NELEM_A);
    split_kernel<<<NELEM_W / 4 / 256, 256>>>(Wq, wh, wl, NELEM_W);
    split_kernel<<<NELEM_W / 4 / 256, 256>>>(Wk, wh + NELEM_W, wl + NELEM_W, NELEM_W);
    split_kernel<<<NELEM_W / 4 / 256, 256>>>(Wv, wh + 2 * NELEM_W, wl + 2 * NELEM_W, NELEM_W);
    split_kernel<<<NELEM_W / 4 / 256, 256>>>(Wo, wh + 3 * NELEM_W, wl + 3 * NELEM_W, NELEM_W);

    gemm_split<<<ggemm, 256, GEMM_SMEM>>>(ah, al, wh + 2 * NELEM_W, wl + 2 * NELEM_W,
                                          vp, SEQ, DIM, DIM);
    // vt_split on side stream, overlapping Q/K GEMMs
    cudaEventRecord(ev_gemmv, 0);
    cudaStreamWaitEvent(s2, ev_gemmv, 0);
    vt_split<<<dim3(DIM / 32, SEQ / 32), dim3(32, 8), 0, s2>>>(vp, vth, vtl);
    cudaEventRecord(ev_vt, s2);

    gemm_split<<<ggemm, 256, GEMM_SMEM>>>(ah, al, wh, wl, qp, SEQ, DIM, DIM);
    gemm_split<<<ggemm, 256, GEMM_SMEM>>>(ah, al, wh + NELEM_W, wl + NELEM_W,
                                          kp, SEQ, DIM, DIM);

    rmsnorm_rope_split<<<dim3(SEQ, NH, 2), HD>>>(qp, kp, qw, kw, cosd, sind,
                                                 qh, ql, kh, kl);

    // join: probs memset + vt must complete before attn
    cudaStreamWaitEvent(0, ev_join, 0);
    cudaStreamWaitEvent(0, ev_vt, 0);

    attn_kernel<<<dim3(SEQ / QBLK, NH), 256, ATT_SMEM>>>(qh, ql, kh, kl, vth, vtl,
                                                         probs, ah, al);

    gemm_split<<<ggemm, 256, GEMM_SMEM>>>(ah, al, wh + 3 * NELEM_W, wl + 3 * NELEM_W,
                                          out, SEQ, DIM, DIM);
}

// round 9
// speedup vs baseline: 2.6238x; 1.0259x over previous
#include <cuda_runtime.h>
#include <cuda_bf16.h>
#include <cstdint>
#include <cstddef>
#include <math.h>

#define SEQ 4096
#define DIM 1024
#define NH 8
#define HD 128
#define WIN 512
#define SCALING 0.0625f
#define SOFTCAP 50.0f
#define EPSV 1e-6f
#define NEGV -1e30f

// scratch (allocation-free rule: device globals)
__device__ float g_q[SEQ * DIM];
__device__ float g_k[SEQ * DIM];
__device__ float g_v[SEQ * DIM];
__device__ __align__(16) __nv_bfloat16 g_ah[SEQ * DIM];
__device__ __align__(16) __nv_bfloat16 g_al[SEQ * DIM];
__device__ __align__(16) __nv_bfloat16 g_wh[4 * DIM * DIM];
__device__ __align__(16) __nv_bfloat16 g_wl[4 * DIM * DIM];
__device__ __align__(16) __nv_bfloat16 g_qh[SEQ * DIM];
__device__ __align__(16) __nv_bfloat16 g_ql[SEQ * DIM];
__device__ __align__(16) __nv_bfloat16 g_kh[SEQ * DIM];
__device__ __align__(16) __nv_bfloat16 g_kl[SEQ * DIM];
__device__ __align__(16) __nv_bfloat16 g_vth[DIM * SEQ];
__device__ __align__(16) __nv_bfloat16 g_vtl[DIM * SEQ];

// ---------------------------------------------------------------------------
// fp32 -> (bf16 hi, bf16 lo) split
// ---------------------------------------------------------------------------
__global__ void split_kernel(const float* __restrict__ x,
                             __nv_bfloat16* __restrict__ hi,
                             __nv_bfloat16* __restrict__ lo, int n)
{
    int i = (blockIdx.x * blockDim.x + threadIdx.x) * 4;
    if (i >= n) return;
    float4 v = *(const float4*)&x[i];
    __nv_bfloat16 h0 = __float2bfloat16_rn(v.x);
    __nv_bfloat16 h1 = __float2bfloat16_rn(v.y);
    __nv_bfloat16 h2 = __float2bfloat16_rn(v.z);
    __nv_bfloat16 h3 = __float2bfloat16_rn(v.w);
    hi[i + 0] = h0; hi[i + 1] = h1; hi[i + 2] = h2; hi[i + 3] = h3;
    lo[i + 0] = __float2bfloat16_rn(v.x - __bfloat162float(h0));
    lo[i + 1] = __float2bfloat16_rn(v.y - __bfloat162float(h1));
    lo[i + 2] = __float2bfloat16_rn(v.z - __bfloat162float(h2));
    lo[i + 3] = __float2bfloat16_rn(v.w - __bfloat162float(h3));
}

// ---------------------------------------------------------------------------
// MMA / async-copy primitives
// ---------------------------------------------------------------------------
__device__ __forceinline__ void ldsm4(uint32_t& r0, uint32_t& r1,
                                      uint32_t& r2, uint32_t& r3, uint32_t addr)
{
    asm volatile("ldmatrix.sync.aligned.m8n8.x4.shared.b16 {%0,%1,%2,%3}, [%4];"
                 : "=r"(r0), "=r"(r1), "=r"(r2), "=r"(r3) : "r"(addr));
}

__device__ __forceinline__ void mma_bf16(float& c0, float& c1, float& c2, float& c3,
                                         uint32_t a0, uint32_t a1, uint32_t a2, uint32_t a3,
                                         uint32_t b0, uint32_t b1)
{
    asm volatile(
        "mma.sync.aligned.m16n8k16.row.col.f32.bf16.bf16.f32 "
        "{%0,%1,%2,%3},{%4,%5,%6,%7},{%8,%9},{%0,%1,%2,%3};"
        : "+f"(c0), "+f"(c1), "+f"(c2), "+f"(c3)
        : "r"(a0), "r"(a1), "r"(a2), "r"(a3), "r"(b0), "r"(b1));
}

__device__ __forceinline__ void cp16(void* smem, const void* gmem)
{
    uint32_t s = (uint32_t)__cvta_generic_to_shared(smem);
    asm volatile("cp.async.cg.shared.global [%0], [%1], 16;" :: "r"(s), "l"(gmem));
}
__device__ __forceinline__ void cp_commit()
{
    asm volatile("cp.async.commit_group;");
}
template <int N>
__device__ __forceinline__ void cp_wait()
{
    asm volatile("cp.async.wait_group %0;" :: "n"(N));
}

// ---------------------------------------------------------------------------
// split-bf16 tensor-core GEMM, cp.async double-buffered.
// C[M,N] = A[M,K] @ B[N,K]^T (fp32 result)
// ---------------------------------------------------------------------------
#define GBM 128
#define GBN 128
#define GBK 32
#define ASTR 40
#define STAGE_ELEMS (4 * GBM * ASTR)
#define GEMM_SMEM (2 * STAGE_ELEMS * 2)

__device__ __forceinline__ void gemm_load_stage(
    __nv_bfloat16* st,
    const __nv_bfloat16* __restrict__ Ah, const __nv_bfloat16* __restrict__ Al,
    const __nv_bfloat16* __restrict__ Bh, const __nv_bfloat16* __restrict__ Bl,
    int m0, int n0, int k0, int K, int tid)
{
#pragma unroll
    for (int p = 0; p < 2; ++p) {
        int idx = tid + p * 256;
        int row = idx >> 2;
        int cc = (idx & 3) * 8;
        cp16(&st[row * ASTR + cc],                  &Ah[(size_t)(m0 + row) * K + k0 + cc]);
        cp16(&st[GBM * ASTR + row * ASTR + cc],     &Al[(size_t)(m0 + row) * K + k0 + cc]);
        cp16(&st[2 * GBM * ASTR + row * ASTR + cc], &Bh[(size_t)(n0 + row) * K + k0 + cc]);
        cp16(&st[3 * GBM * ASTR + row * ASTR + cc], &Bl[(size_t)(n0 + row) * K + k0 + cc]);
    }
}

__global__ __launch_bounds__(256) void gemm_split(
    const __nv_bfloat16* __restrict__ Ah, const __nv_bfloat16* __restrict__ Al,
    const __nv_bfloat16* __restrict__ Bh, const __nv_bfloat16* __restrict__ Bl,
    float* __restrict__ C, int M, int N, int K)
{
    extern __shared__ char dynsm[];
    __nv_bfloat16* buf = (__nv_bfloat16*)dynsm;

    int tid = threadIdx.x;
    int lane = tid & 31;
    int w = tid >> 5;
    int wm = w & 1;
    int wn = w >> 1;
    int m0 = blockIdx.y * GBM;
    int n0 = blockIdx.x * GBN;

    float c[4][4][4] = {};

    int g = lane >> 3, r8 = lane & 7;
    int a_row_off = (g & 1) * 8;
    int a_k_off = (g >> 1) * 8;
    int b_n_off = (g >> 1) * 8;
    int b_k_off = (g & 1) * 8;

    gemm_load_stage(buf, Ah, Al, Bh, Bl, m0, n0, 0, K, tid);
    cp_commit();

    int p = 0;
    for (int k0 = 0; k0 < K; k0 += GBK) {
        cp_wait<0>();
        __syncthreads();
        if (k0 + GBK < K) {
            gemm_load_stage(buf + (p ^ 1) * STAGE_ELEMS, Ah, Al, Bh, Bl,
                            m0, n0, k0 + GBK, K, tid);
            cp_commit();
        }
        __nv_bfloat16* sAh = buf + p * STAGE_ELEMS;
        __nv_bfloat16* sAl = sAh + GBM * ASTR;
        __nv_bfloat16* sBh = sAl + GBM * ASTR;
        __nv_bfloat16* sBl = sBh + GBM * ASTR;

#pragma unroll
        for (int ks = 0; ks < GBK; ks += 16) {
            uint32_t ah[4][4], al[4][4], bh[4][2], bl[4][2];
#pragma unroll
            for (int mt = 0; mt < 4; ++mt) {
                int roff = (wm * 64 + mt * 16 + a_row_off + r8) * ASTR + ks + a_k_off;
                ldsm4(ah[mt][0], ah[mt][1], ah[mt][2], ah[mt][3],
                      (uint32_t)__cvta_generic_to_shared(&sAh[roff]));
                ldsm4(al[mt][0], al[mt][1], al[mt][2], al[mt][3],
                      (uint32_t)__cvta_generic_to_shared(&sAl[roff]));
            }
#pragma unroll
            for (int ntp = 0; ntp < 2; ++ntp) {
                int roff = (wn * 32 + ntp * 16 + b_n_off + r8) * ASTR + ks + b_k_off;
                ldsm4(bh[ntp * 2][0], bh[ntp * 2][1], bh[ntp * 2 + 1][0], bh[ntp * 2 + 1][1],
                      (uint32_t)__cvta_generic_to_shared(&sBh[roff]));
                ldsm4(bl[ntp * 2][0], bl[ntp * 2][1], bl[ntp * 2 + 1][0], bl[ntp * 2 + 1][1],
                      (uint32_t)__cvta_generic_to_shared(&sBl[roff]));
            }
#pragma unroll
            for (int mt = 0; mt < 4; ++mt)
#pragma unroll
                for (int nt = 0; nt < 4; ++nt) {
                    float* cc = c[mt][nt];
                    mma_bf16(cc[0], cc[1], cc[2], cc[3],
                             ah[mt][0], ah[mt][1], ah[mt][2], ah[mt][3],
                             bh[nt][0], bh[nt][1]);
                    mma_bf16(cc[0], cc[1], cc[2], cc[3],
                             ah[mt][0], ah[mt][1], ah[mt][2], ah[mt][3],
                             bl[nt][0], bl[nt][1]);
                    mma_bf16(cc[0], cc[1], cc[2], cc[3],
                             al[mt][0], al[mt][1], al[mt][2], al[mt][3],
                             bh[nt][0], bh[nt][1]);
                }
        }
        p ^= 1;
    }

#pragma unroll
    for (int mt = 0; mt < 4; ++mt) {
#pragma unroll
        for (int nt = 0; nt < 4; ++nt) {
            int row = m0 + wm * 64 + mt * 16 + (lane >> 2);
            int col = n0 + wn * 32 + nt * 8 + 2 * (lane & 3);
            float* cc = c[mt][nt];
            *(float2*)&C[(size_t)row * N + col] = make_float2(cc[0], cc[1]);
            *(float2*)&C[(size_t)(row + 8) * N + col] = make_float2(cc[2], cc[3]);
        }
    }
}

// ---------------------------------------------------------------------------
// Fused RMSNorm + RoPE for ONE tensor; emits split bf16. grid (S, H), block 128.
// ---------------------------------------------------------------------------
__global__ void rmsnorm_rope_split(
    const float* __restrict__ x0, const float* __restrict__ w,
    const float* __restrict__ cosd, const float* __restrict__ sind,
    __nv_bfloat16* __restrict__ oh, __nv_bfloat16* __restrict__ ol)
{
    int s = blockIdx.x;
    int h = blockIdx.y;
    int d = threadIdx.x;

    const float* x = x0 + (size_t)s * DIM + h * HD;

    float xd = x[d];
    int p = d ^ 64;
    float xp = x[p];

    float v = xd * xd;
#pragma unroll
    for (int off = 16; off; off >>= 1)
        v += __shfl_xor_sync(0xffffffffu, v, off);
    __shared__ float red[4];
    if ((d & 31) == 0) red[d >> 5] = v;
    __syncthreads();
    float var = (red[0] + red[1] + red[2] + red[3]) * (1.0f / HD);
    float rs = rsqrtf(var + EPSV);

    float xnd = xd * rs * (1.0f + w[d]);
    float xnp = xp * rs * (1.0f + w[p]);
    float c = cosd[(size_t)s * HD + d];
    float si = sind[(size_t)s * HD + d];
    float rot = (d < 64) ? -xnp : xnp;
    float outv = xnd * c + rot * si;

    size_t idx = (size_t)s * DIM + h * HD + d;
    __nv_bfloat16 hh = __float2bfloat16_rn(outv);
    oh[idx] = hh;
    ol[idx] = __float2bfloat16_rn(outv - __bfloat162float(hh));
}

// ---------------------------------------------------------------------------
// V transpose + split
// ---------------------------------------------------------------------------
__global__ void vt_split(const float* __restrict__ v,
                         __nv_bfloat16* __restrict__ vth,
                         __nv_bfloat16* __restrict__ vtl)
{
    __shared__ float tile[32][33];
    int d0 = blockIdx.x * 32;
    int s0 = blockIdx.y * 32;
    int tx = threadIdx.x, ty = threadIdx.y;
#pragma unroll
    for (int i = 0; i < 4; ++i) {
        int s = s0 + ty + i * 8;
        tile[ty + i * 8][tx] = v[(size_t)s * DIM + d0 + tx];
    }
    __syncthreads();
#pragma unroll
    for (int i = 0; i < 4; ++i) {
        int d = d0 + ty + i * 8;
        int s = s0 + tx;
        float val = tile[tx][ty + i * 8];
        __nv_bfloat16 hh = __float2bfloat16_rn(val);
        vth[(size_t)d * SEQ + s] = hh;
        vtl[(size_t)d * SEQ + s] = __float2bfloat16_rn(val - __bfloat162float(hh));
    }
}

// ---------------------------------------------------------------------------
// Windowed attention, tensor-core + register-staged prefetch (round-8).
// ---------------------------------------------------------------------------
#define QBLK 64
#define KT 64
#define NTILE 9
#define SLABW 580
#define QKSTR 136
#define PSTR 72

#define ATT_A_OFF (QBLK * SLABW * 4)
#define ATT_B_OFF (ATT_A_OFF + 2 * QBLK * QKSTR * 2)
#define ATT_SMEM  (ATT_B_OFF + 2 * HD * PSTR * 2)

__global__ __launch_bounds__(256) void attn_kernel(
    const __nv_bfloat16* __restrict__ gqh, const __nv_bfloat16* __restrict__ gql,
    const __nv_bfloat16* __restrict__ gkh, const __nv_bfloat16* __restrict__ gkl,
    const __nv_bfloat16* __restrict__ gvth, const __nv_bfloat16* __restrict__ gvtl,
    float* __restrict__ probs,
    __nv_bfloat16* __restrict__ oh, __nv_bfloat16* __restrict__ ol)
{
    extern __shared__ char smc[];
    float* slab = (float*)smc;
    __nv_bfloat16* Qh = (__nv_bfloat16*)(smc + ATT_A_OFF);
    __nv_bfloat16* Ql = Qh + QBLK * QKSTR;
    __nv_bfloat16* Ph = (__nv_bfloat16*)(smc + ATT_A_OFF);
    __nv_bfloat16* Pl = Ph + QBLK * PSTR;
    __nv_bfloat16* Kh = (__nv_bfloat16*)(smc + ATT_B_OFF);
    __nv_bfloat16* Kl = Kh + QBLK * QKSTR;
    __nv_bfloat16* Vh = (__nv_bfloat16*)(smc + ATT_B_OFF);
    __nv_bfloat16* Vl = Vh + HD * PSTR;
    __shared__ float rowscale[QBLK];

    int qb0 = blockIdx.x * QBLK;
    int h = blockIdx.y;
    int tid = threadIdx.x;
    int lane = tid & 31;
    int w = tid >> 5;
    int wm = w & 3;
    int wn = w >> 2;
    int kbase = qb0 - WIN;
    int t_start = (qb0 >= WIN) ? 0 : (WIN - qb0) / KT;
    int c0 = t_start * KT;

    int g = lane >> 3, r8 = lane & 7;
    int a_row_off = (g & 1) * 8;
    int a_k_off = (g >> 1) * 8;
    int b_n_off = (g >> 1) * 8;
    int b_k_off = (g & 1) * 8;
    int qg = lane >> 2, t4 = lane & 3;

    // ---- load Q tiles (hi/lo) ----
#pragma unroll
    for (int i = 0; i < 4; ++i) {
        int idx = tid + i * 256;
        int row = idx >> 4;
        int c8 = (idx & 15) * 8;
        size_t goff = (size_t)(qb0 + row) * DIM + h * HD + c8;
        *(uint4*)&Qh[row * QKSTR + c8] = *(const uint4*)&gqh[goff];
        *(uint4*)&Ql[row * QKSTR + c8] = *(const uint4*)&gql[goff];
    }

    // ================= scores (register-staged prefetch) =================
    uint4 pkh[4], pkl[4];
    {
        int kstart = kbase + t_start * KT;
#pragma unroll
        for (int i = 0; i < 4; ++i) {
            int idx = tid + i * 256;
            int row = idx >> 4;
            int c8 = (idx & 15) * 8;
            size_t goff = (size_t)(kstart + row) * DIM + h * HD + c8;
            pkh[i] = *(const uint4*)&gkh[goff];
            pkl[i] = *(const uint4*)&gkl[goff];
        }
    }

    for (int t = t_start; t < NTILE; ++t) {
        __syncthreads();
#pragma unroll
        for (int i = 0; i < 4; ++i) {
            int idx = tid + i * 256;
            int row = idx >> 4;
            int c8 = (idx & 15) * 8;
            *(uint4*)&Kh[row * QKSTR + c8] = pkh[i];
            *(uint4*)&Kl[row * QKSTR + c8] = pkl[i];
        }
        __syncthreads();
        if (t + 1 < NTILE) {
            int kstart = kbase + (t + 1) * KT;
#pragma unroll
            for (int i = 0; i < 4; ++i) {
                int idx = tid + i * 256;
                int row = idx >> 4;
                int c8 = (idx & 15) * 8;
                size_t goff = (size_t)(kstart + row) * DIM + h * HD + c8;
                pkh[i] = *(const uint4*)&gkh[goff];
                pkl[i] = *(const uint4*)&gkl[goff];
            }
        }

        float acc[4][4] = {};
#pragma unroll
        for (int ks = 0; ks < 8; ++ks) {
            uint32_t qhf[4], qlf[4], bhf[4][2], blf[4][2];
            int aoff = (wm * 16 + a_row_off + r8) * QKSTR + ks * 16 + a_k_off;
            ldsm4(qhf[0], qhf[1], qhf[2], qhf[3],
                  (uint32_t)__cvta_generic_to_shared(&Qh[aoff]));
            ldsm4(qlf[0], qlf[1], qlf[2], qlf[3],
                  (uint32_t)__cvta_generic_to_shared(&Ql[aoff]));
#pragma unroll
            for (int ntp = 0; ntp < 2; ++ntp) {
                int boff = (wn * 32 + ntp * 16 + b_n_off + r8) * QKSTR + ks * 16 + b_k_off;
                ldsm4(bhf[ntp * 2][0], bhf[ntp * 2][1],
                      bhf[ntp * 2 + 1][0], bhf[ntp * 2 + 1][1],
                      (uint32_t)__cvta_generic_to_shared(&Kh[boff]));
                ldsm4(blf[ntp * 2][0], blf[ntp * 2][1],
                      blf[ntp * 2 + 1][0], blf[ntp * 2 + 1][1],
                      (uint32_t)__cvta_generic_to_shared(&Kl[boff]));
            }
#pragma unroll
            for (int nt = 0; nt < 4; ++nt) {
                float* cc = acc[nt];
                mma_bf16(cc[0], cc[1], cc[2], cc[3],
                         qhf[0], qhf[1], qhf[2], qhf[3], bhf[nt][0], bhf[nt][1]);
                mma_bf16(cc[0], cc[1], cc[2], cc[3],
                         qhf[0], qhf[1], qhf[2], qhf[3], blf[nt][0], blf[nt][1]);
                mma_bf16(cc[0], cc[1], cc[2], cc[3],
                         qlf[0], qlf[1], qlf[2], qlf[3], bhf[nt][0], bhf[nt][1]);
            }
        }

#pragma unroll
        for (int nt = 0; nt < 4; ++nt) {
#pragma unroll
            for (int e = 0; e < 4; ++e) {
                int r = wm * 16 + qg + (e >> 1) * 8;
                int cw = wn * 32 + nt * 8 + 2 * t4 + (e & 1);
                int qi = qb0 + r;
                int kj = kbase + t * KT + cw;
                float x = acc[nt][e] * (SCALING / SOFTCAP);
                float ex = __expf(2.0f * x);
                float sv = SOFTCAP * __fdividef(ex - 1.0f, ex + 1.0f);
                bool ok = (kj <= qi) && (qi - kj < WIN);
                slab[r * SLABW + t * KT + cw] = ok ? sv : NEGV;
            }
        }
    }
    __syncthreads();

    // ================= softmax (exact) =================
    for (int r = w * 8; r < w * 8 + 8; ++r) {
        float m = NEGV;
        for (int c = c0 + lane; c < NTILE * KT; c += 32)
            m = fmaxf(m, slab[r * SLABW + c]);
#pragma unroll
        for (int off = 16; off; off >>= 1)
            m = fmaxf(m, __shfl_xor_sync(0xffffffffu, m, off));
        float ssum = 0.0f;
        for (int c = c0 + lane; c < NTILE * KT; c += 32) {
            float e = __expf(slab[r * SLABW + c] - m);
            slab[r * SLABW + c] = e;
            ssum += e;
        }
#pragma unroll
        for (int off = 16; off; off >>= 1)
            ssum += __shfl_xor_sync(0xffffffffu, ssum, off);
        if (lane == 0) rowscale[r] = 1.0f / ssum;
    }
    __syncthreads();

    // ================= probs band write =================
    for (int f = tid; f < QBLK * (NTILE * KT / 4); f += 256) {
        int row = f / (NTILE * KT / 4);
        int col = (f % (NTILE * KT / 4)) * 4;
        if (col < c0) continue;
        int j = kbase + col;
        float sc = rowscale[row];
        float4 e = *(const float4*)&slab[row * SLABW + col];
        float4 o = make_float4(e.x * sc, e.y * sc, e.z * sc, e.w * sc);
        *(float4*)&probs[(size_t)h * SEQ * SEQ + (size_t)(qb0 + row) * SEQ + j] = o;
    }

    // ================= P @ V (register-staged prefetch) =================
    uint4 pvh[4], pvl[4];
    {
        int kstart = kbase + t_start * KT;
#pragma unroll
        for (int i = 0; i < 4; ++i) {
            int idx = tid + i * 256;
            int row = idx >> 3;
            int c8 = (idx & 7) * 8;
            size_t goff = (size_t)(h * HD + row) * SEQ + kstart + c8;
            pvh[i] = *(const uint4*)&gvth[goff];
            pvl[i] = *(const uint4*)&gvtl[goff];
        }
    }

    float oacc[8][4] = {};
    for (int t = t_start; t < NTILE; ++t) {
        __syncthreads();
#pragma unroll
        for (int i = 0; i < 4; ++i) {
            int idx = tid + i * 256;
            int row = idx >> 4;
            int c4 = (idx & 15) * 4;
            float4 p = *(const float4*)&slab[row * SLABW + t * KT + c4];
            __nv_bfloat16 h0 = __float2bfloat16_rn(p.x);
            __nv_bfloat16 h1 = __float2bfloat16_rn(p.y);
            __nv_bfloat16 h2 = __float2bfloat16_rn(p.z);
            __nv_bfloat16 h3 = __float2bfloat16_rn(p.w);
            Ph[row * PSTR + c4 + 0] = h0;
            Ph[row * PSTR + c4 + 1] = h1;
            Ph[row * PSTR + c4 + 2] = h2;
            Ph[row * PSTR + c4 + 3] = h3;
            Pl[row * PSTR + c4 + 0] = __float2bfloat16_rn(p.x - __bfloat162float(h0));
            Pl[row * PSTR + c4 + 1] = __float2bfloat16_rn(p.y - __bfloat162float(h1));
            Pl[row * PSTR + c4 + 2] = __float2bfloat16_rn(p.z - __bfloat162float(h2));
            Pl[row * PSTR + c4 + 3] = __float2bfloat16_rn(p.w - __bfloat162float(h3));
        }
#pragma unroll
        for (int i = 0; i < 4; ++i) {
            int idx = tid + i * 256;
            int row = idx >> 3;
            int c8 = (idx & 7) * 8;
            *(uint4*)&Vh[row * PSTR + c8] = pvh[i];
            *(uint4*)&Vl[row * PSTR + c8] = pvl[i];
        }
        __syncthreads();
        if (t + 1 < NTILE) {
            int kstart = kbase + (t + 1) * KT;
#pragma unroll
            for (int i = 0; i < 4; ++i) {
                int idx = tid + i * 256;
                int row = idx >> 3;
                int c8 = (idx & 7) * 8;
                size_t goff = (size_t)(h * HD + row) * SEQ + kstart + c8;
                pvh[i] = *(const uint4*)&gvth[goff];
                pvl[i] = *(const uint4*)&gvtl[goff];
            }
        }

#pragma unroll
        for (int ks = 0; ks < 4; ++ks) {
            uint32_t phf[4], plf[4], vhf[8][2], vlf[8][2];
            int aoff = (wm * 16 + a_row_off + r8) * PSTR + ks * 16 + a_k_off;
            ldsm4(phf[0], phf[1], phf[2], phf[3],
                  (uint32_t)__cvta_generic_to_shared(&Ph[aoff]));
            ldsm4(plf[0], plf[1], plf[2], plf[3],
                  (uint32_t)__cvta_generic_to_shared(&Pl[aoff]));
#pragma unroll
            for (int ntp = 0; ntp < 4; ++ntp) {
                int boff = (wn * 64 + ntp * 16 + b_n_off + r8) * PSTR + ks * 16 + b_k_off;
                ldsm4(vhf[ntp * 2][0], vhf[ntp * 2][1],
                      vhf[ntp * 2 + 1][0], vhf[ntp * 2 + 1][1],
                      (uint32_t)__cvta_generic_to_shared(&Vh[boff]));
                ldsm4(vlf[ntp * 2][0], vlf[ntp * 2][1],
                      vlf[ntp * 2 + 1][0], vlf[ntp * 2 + 1][1],
                      (uint32_t)__cvta_generic_to_shared(&Vl[boff]));
            }
#pragma unroll
            for (int nt = 0; nt < 8; ++nt) {
                float* cc = oacc[nt];
                mma_bf16(cc[0], cc[1], cc[2], cc[3],
                         phf[0], phf[1], phf[2], phf[3], vhf[nt][0], vhf[nt][1]);
                mma_bf16(cc[0], cc[1], cc[2], cc[3],
                         phf[0], phf[1], phf[2], phf[3], vlf[nt][0], vlf[nt][1]);
                mma_bf16(cc[0], cc[1], cc[2], cc[3],
                         plf[0], plf[1], plf[2], plf[3], vhf[nt][0], vhf[nt][1]);
            }
        }
    }

    // ---- write O (scaled by 1/rowsum) as split bf16 ----
    {
        int r0 = wm * 16 + qg;
        int r1 = r0 + 8;
        float sc0 = rowscale[r0];
        float sc1 = rowscale[r1];
#pragma unroll
        for (int nt = 0; nt < 8; ++nt) {
            int col = wn * 64 + nt * 8 + 2 * t4;
            float* cc = oacc[nt];
            float f00 = cc[0] * sc0, f01 = cc[1] * sc0;
            float f10 = cc[2] * sc1, f11 = cc[3] * sc1;
            size_t o0 = (size_t)(qb0 + r0) * DIM + h * HD + col;
            size_t o1 = (size_t)(qb0 + r1) * DIM + h * HD + col;
            __nv_bfloat16 h00 = __float2bfloat16_rn(f00);
            __nv_bfloat16 h01 = __float2bfloat16_rn(f01);
            __nv_bfloat16 h10 = __float2bfloat16_rn(f10);
            __nv_bfloat16 h11 = __float2bfloat16_rn(f11);
            *(__nv_bfloat162*)&oh[o0] = __nv_bfloat162(h00, h01);
            *(__nv_bfloat162*)&oh[o1] = __nv_bfloat162(h10, h11);
            *(__nv_bfloat162*)&ol[o0] = __nv_bfloat162(
                __float2bfloat16_rn(f00 - __bfloat162float(h00)),
                __float2bfloat16_rn(f01 - __bfloat162float(h01)));
            *(__nv_bfloat162*)&ol[o1] = __nv_bfloat162(
                __float2bfloat16_rn(f10 - __bfloat162float(h10)),
                __float2bfloat16_rn(f11 - __bfloat162float(h11)));
        }
    }
}

// ---------------------------------------------------------------------------
extern "C" void kernel_launch(void* const* d_in, const int* in_sizes, int n_in,
                              void* d_out, int out_size)
{
    (void)in_sizes; (void)n_in; (void)out_size;
    const float* hidden = (const float*)d_in[0];
    const float* cosd   = (const float*)d_in[1];
    const float* sind   = (const float*)d_in[2];
    const float* Wq     = (const float*)d_in[3];
    const float* Wk     = (const float*)d_in[4];
    const float* Wv     = (const float*)d_in[5];
    const float* Wo     = (const float*)d_in[6];
    const float* qw     = (const float*)d_in[7];
    const float* kw     = (const float*)d_in[8];

    float* out = (float*)d_out;
    float* probs = out + (size_t)SEQ * DIM;

    float *qp, *kp, *vp;
    cudaGetSymbolAddress((void**)&qp, g_q);
    cudaGetSymbolAddress((void**)&kp, g_k);
    cudaGetSymbolAddress((void**)&vp, g_v);
    __nv_bfloat16 *ah, *al, *wh, *wl, *qh, *ql, *kh, *kl, *vth, *vtl;
    cudaGetSymbolAddress((void**)&ah, g_ah);
    cudaGetSymbolAddress((void**)&al, g_al);
    cudaGetSymbolAddress((void**)&wh, g_wh);
    cudaGetSymbolAddress((void**)&wl, g_wl);
    cudaGetSymbolAddress((void**)&qh, g_qh);
    cudaGetSymbolAddress((void**)&ql, g_ql);
    cudaGetSymbolAddress((void**)&kh, g_kh);
    cudaGetSymbolAddress((void**)&kl, g_kl);
    cudaGetSymbolAddress((void**)&vth, g_vth);
    cudaGetSymbolAddress((void**)&vtl, g_vtl);

    // lazy one-time resources (created on first, non-capturing, call)
    static cudaStream_t s2 = nullptr, s3 = nullptr;
    static cudaEvent_t ev_fork = nullptr, ev_join = nullptr;
    static cudaEvent_t ev_gemmv = nullptr, ev_vt = nullptr;
    static cudaEvent_t ev_wo = nullptr, ev_gq = nullptr, ev_rmsq = nullptr;
    static bool smem_set = false;
    if (!s2) {
        cudaStreamCreateWithFlags(&s2, cudaStreamNonBlocking);
        cudaStreamCreateWithFlags(&s3, cudaStreamNonBlocking);
        cudaEventCreateWithFlags(&ev_fork, cudaEventDisableTiming);
        cudaEventCreateWithFlags(&ev_join, cudaEventDisableTiming);
        cudaEventCreateWithFlags(&ev_gemmv, cudaEventDisableTiming);
        cudaEventCreateWithFlags(&ev_vt, cudaEventDisableTiming);
        cudaEventCreateWithFlags(&ev_wo, cudaEventDisableTiming);
        cudaEventCreateWithFlags(&ev_gq, cudaEventDisableTiming);
        cudaEventCreateWithFlags(&ev_rmsq, cudaEventDisableTiming);
    }
    if (!smem_set) {
        cudaFuncSetAttribute(gemm_split,
                             cudaFuncAttributeMaxDynamicSharedMemorySize, GEMM_SMEM);
        cudaFuncSetAttribute(attn_kernel,
                             cudaFuncAttributeMaxDynamicSharedMemorySize, ATT_SMEM);
        smem_set = true;
    }

    const int NELEM_A = SEQ * DIM, NELEM_W = DIM * DIM;
    dim3 ggemm(DIM / GBN, SEQ / GBM);

    // fork side streams off the capture origin
    cudaEventRecord(ev_fork, 0);
    cudaStreamWaitEvent(s2, ev_fork, 0);
    cudaStreamWaitEvent(s3, ev_fork, 0);

    // submission 1: memset on s2 (overlaps everything up to attn)
    cudaMemsetAsync(probs, 0, (size_t)NH * SEQ * SEQ * sizeof(float), s2);
    cudaEventRecord(ev_join, s2);

    // submissions 2..5 (main): splits needed for the first GEMMs
    split_kernel<<<NELEM_A / 4 / 256, 256>>>(hidden, ah, al, NELEM_A);
    split_kernel<<<NELEM_W / 4 / 256, 256>>>(Wq, wh, wl, NELEM_W);
    split_kernel<<<NELEM_W / 4 / 256, 256>>>(Wk, wh + NELEM_W, wl + NELEM_W, NELEM_W);
    split_kernel<<<NELEM_W / 4 / 256, 256>>>(Wv, wh + 2 * NELEM_W, wl + 2 * NELEM_W, NELEM_W);

    // submission 6: V GEMM -> profiled by ncu (-s 5 -c 1)
    gemm_split<<<ggemm, 256, GEMM_SMEM>>>(ah, al, wh + 2 * NELEM_W, wl + 2 * NELEM_W,
                                          vp, SEQ, DIM, DIM);

    // Wo split on s3 (independent; overlaps V/Q/K GEMMs)
    split_kernel<<<NELEM_W / 4 / 256, 256, 0, s3>>>(Wo, wh + 3 * NELEM_W,
                                                    wl + 3 * NELEM_W, NELEM_W);
    cudaEventRecord(ev_wo, s3);

    // vt_split on s2, after V GEMM (overlaps Q/K GEMMs)
    cudaEventRecord(ev_gemmv, 0);
    cudaStreamWaitEvent(s2, ev_gemmv, 0);
    vt_split<<<dim3(DIM / 32, SEQ / 32), dim3(32, 8), 0, s2>>>(vp, vth, vtl);
    cudaEventRecord(ev_vt, s2);

    // Q GEMM, then rmsnorm-Q on s3 overlapping the K GEMM
    gemm_split<<<ggemm, 256, GEMM_SMEM>>>(ah, al, wh, wl, qp, SEQ, DIM, DIM);
    cudaEventRecord(ev_gq, 0);
    cudaStreamWaitEvent(s3, ev_gq, 0);
    rmsnorm_rope_split<<<dim3(SEQ, NH), HD, 0, s3>>>(qp, qw, cosd, sind, qh, ql);
    cudaEventRecord(ev_rmsq, s3);

    gemm_split<<<ggemm, 256, GEMM_SMEM>>>(ah, al, wh + NELEM_W, wl + NELEM_W,
                                          kp, SEQ, DIM, DIM);
    rmsnorm_rope_split<<<dim3(SEQ, NH), HD>>>(kp, kw, cosd, sind, kh, kl);

    // join: memset, vt, rmsnorm-Q must complete before attn
    cudaStreamWaitEvent(0, ev_join, 0);
    cudaStreamWaitEvent(0, ev_vt, 0);
    cudaStreamWaitEvent(0, ev_rmsq, 0);

    attn_kernel<<<dim3(SEQ / QBLK, NH), 256, ATT_SMEM>>>(qh, ql, kh, kl, vth, vtl,
                                                         probs, ah, al);

    // O projection needs Wo split
    cudaStreamWaitEvent(0, ev_wo, 0);
    gemm_split<<<ggemm, 256, GEMM_SMEM>>>(ah, al, wh + 3 * NELEM_W, wl + 3 * NELEM_W,
                                          out, SEQ, DIM, DIM);
}